// round 5
// baseline (speedup 1.0000x reference)
#include <cuda_runtime.h>
#include <cuda_fp16.h>
#include <math.h>
#include <stdint.h>

#define T_TOK 4096
#define DIM   1024
#define NEXP  8
#define HID   2816
#define NSLOT (T_TOK*2)

typedef unsigned long long ull;

// ---------------- device scratch (static, no allocs) ----------------
__device__ __align__(16) __half g_xh[(size_t)T_TOK*DIM];
__device__ __align__(16) __half g_xl[(size_t)T_TOK*DIM];
__device__ __align__(16) __half g_Hh[(size_t)NSLOT*HID];
__device__ __align__(16) __half g_Hl[(size_t)NSLOT*HID];
__device__ int   g_tok[NSLOT];
__device__ float g_wslot[NSLOT];
__device__ int   g_te[NSLOT];
__device__ float g_tw[NSLOT];
__device__ int   g_cnt[NEXP];
__device__ int   g_off[NEXP + 1];
__device__ int   g_cur[NEXP];

// ---------------- helpers ----------------
__device__ __forceinline__ uint32_t s2u(const void* p) {
    uint32_t a;
    asm("{ .reg .u64 t; cvta.to.shared.u64 t, %1; cvt.u32.u64 %0, t; }" : "=r"(a) : "l"(p));
    return a;
}
__device__ __forceinline__ unsigned hpack(float lo_elem, float hi_elem) {
    unsigned r;
    asm("cvt.rn.f16x2.f32 %0, %1, %2;" : "=r"(r) : "f"(hi_elem), "f"(lo_elem));
    return r;
}
__device__ __forceinline__ ull f4toh4(float4 v) {
    unsigned p0 = hpack(v.x, v.y);
    unsigned p1 = hpack(v.z, v.w);
    return (ull)p0 | ((ull)p1 << 32);
}
__device__ __forceinline__ void ldm4(uint32_t& r0, uint32_t& r1, uint32_t& r2, uint32_t& r3, uint32_t a) {
    asm volatile("ldmatrix.sync.aligned.m8n8.x4.shared.b16 {%0,%1,%2,%3}, [%4];"
        : "=r"(r0), "=r"(r1), "=r"(r2), "=r"(r3) : "r"(a));
}
__device__ __forceinline__ void mma16816(float* c, const uint32_t* a, const uint32_t* b) {
    asm volatile("mma.sync.aligned.m16n8k16.row.col.f32.f16.f16.f32 "
        "{%0,%1,%2,%3}, {%4,%5,%6,%7}, {%8,%9}, {%0,%1,%2,%3};"
        : "+f"(c[0]), "+f"(c[1]), "+f"(c[2]), "+f"(c[3])
        : "r"(a[0]), "r"(a[1]), "r"(a[2]), "r"(a[3]), "r"(b[0]), "r"(b[1]));
}
__device__ __forceinline__ void cpa16(uint32_t dst, const void* src) {
    asm volatile("cp.async.cg.shared.global [%0], [%1], 16;" :: "r"(dst), "l"(src) : "memory");
}
#define CP_COMMIT() asm volatile("cp.async.commit_group;" ::: "memory")
#define CP_WAIT2()  asm volatile("cp.async.wait_group 2;" ::: "memory")

// smem geometry (halves): rows padded to 40 (k32 + 8)
#define ROWP   40
#define A_STG  10240                 // Ah(5120) + Al(5120) per stage
#define A_TOT  (4*A_STG)             // 4 stages
#define B1_STG 5120                  // B1(2560) + B2(2560)
#define B2_STG 2560                  // B(2560)
#define SMEM1  ((A_TOT + 2*B1_STG)*2)
#define SMEM2  ((A_TOT + 2*B2_STG)*2)

// ---------------- small kernels ----------------
__global__ void k_zero_cnt() { if (threadIdx.x < NEXP) g_cnt[threadIdx.x] = 0; }

__global__ void k_zero_out(float4* o) {
    o[blockIdx.x * 256 + threadIdx.x] = make_float4(0.f, 0.f, 0.f, 0.f);
}

// gating + split x into planar fp16 hi/lo
__global__ void k_gate(const float* __restrict__ x, const float* __restrict__ Wg) {
    int t = (blockIdx.x * blockDim.x + threadIdx.x) >> 5;
    int lane = threadIdx.x & 31;
    if (t >= T_TOK) return;
    const float4* xr = reinterpret_cast<const float4*>(x + (size_t)t * DIM);
    float s[NEXP];
#pragma unroll
    for (int e = 0; e < NEXP; e++) s[e] = 0.f;
    for (int i = lane; i < DIM / 4; i += 32) {
        float4 xv = xr[i];
#pragma unroll
        for (int e = 0; e < NEXP; e++) {
            float4 wv = reinterpret_cast<const float4*>(Wg + (size_t)e * DIM)[i];
            s[e] += xv.x * wv.x + xv.y * wv.y + xv.z * wv.z + xv.w * wv.w;
        }
        // split-store x
        unsigned h01 = hpack(xv.x, xv.y);
        unsigned h23 = hpack(xv.z, xv.w);
        float f0 = __half2float(__ushort_as_half((unsigned short)(h01 & 0xffff)));
        float f1 = __half2float(__ushort_as_half((unsigned short)(h01 >> 16)));
        float f2 = __half2float(__ushort_as_half((unsigned short)(h23 & 0xffff)));
        float f3 = __half2float(__ushort_as_half((unsigned short)(h23 >> 16)));
        unsigned l01 = hpack(xv.x - f0, xv.y - f1);
        unsigned l23 = hpack(xv.z - f2, xv.w - f3);
        *(uint2*)(g_xh + (size_t)t * DIM + i * 4) = make_uint2(h01, h23);
        *(uint2*)(g_xl + (size_t)t * DIM + i * 4) = make_uint2(l01, l23);
    }
#pragma unroll
    for (int e = 0; e < NEXP; e++) {
#pragma unroll
        for (int o = 16; o > 0; o >>= 1) s[e] += __shfl_xor_sync(0xffffffffu, s[e], o);
    }
    if (lane == 0) {
        int b0 = 0; float v0 = s[0];
#pragma unroll
        for (int e = 1; e < NEXP; e++) if (s[e] > v0) { v0 = s[e]; b0 = e; }
        int b1 = -1; float v1 = -3.4e38f;
#pragma unroll
        for (int e = 0; e < NEXP; e++) if (e != b0 && s[e] > v1) { v1 = s[e]; b1 = e; }
        g_te[t * 2 + 0] = b0;  g_te[t * 2 + 1] = b1;
        g_tw[t * 2 + 0] = v0;  g_tw[t * 2 + 1] = v1;
        atomicAdd(&g_cnt[b0], 1);
        atomicAdd(&g_cnt[b1], 1);
    }
}

__global__ void k_scan() {
    int o = 0;
    for (int e = 0; e < NEXP; e++) { g_off[e] = o; g_cur[e] = o; o += g_cnt[e]; }
    g_off[NEXP] = o;
}

__global__ void k_assign() {
    int t = blockIdx.x * blockDim.x + threadIdx.x;
    if (t >= T_TOK) return;
#pragma unroll
    for (int k = 0; k < 2; k++) {
        int e = g_te[t * 2 + k];
        int pos = atomicAdd(&g_cur[e], 1);
        g_tok[pos] = t;
        g_wslot[pos] = g_tw[t * 2 + k];
    }
}

// ---------------- shared staging pieces ----------------
// A via cp.async: 4 x 16B per thread (2 for hi plane, 2 for lo plane)
__device__ __forceinline__ void cpA(uint32_t smb, int soff, int tid, const int* s_idx,
                                    const __half* __restrict__ ah, const __half* __restrict__ al,
                                    int rowstride, int k0) {
#pragma unroll
    for (int i = 0; i < 2; i++) {
        int op = tid + (i << 8); int r = op >> 2, g = op & 3;
        size_t so = (size_t)s_idx[r] * rowstride + k0 + g * 8;
        uint32_t d = smb + (uint32_t)(soff + r * ROWP + g * 8) * 2;
        cpa16(d, ah + so);
        cpa16(d + 5120 * 2, al + so);
    }
}

// ---------------- GEMM1 ----------------
__device__ __forceinline__ void comp1(uint32_t smb, int ast, int bst, int wid, int lane,
                                      float (&A1)[2][4][4], float (&A2)[2][4][4]) {
    int aoff = ast * A_STG;
    int boff = A_TOT + bst * B1_STG;
#pragma unroll
    for (int ks = 0; ks < 2; ks++) {
        uint32_t ah[2][4], al[2][4];
#pragma unroll
        for (int mt = 0; mt < 2; mt++) {
            int row = (wid & 3) * 32 + mt * 16 + (lane & 15);
            int hc = ks * 16 + ((lane & 16) >> 1);
            uint32_t ad = smb + (uint32_t)(aoff + row * ROWP + hc) * 2;
            ldm4(ah[mt][0], ah[mt][1], ah[mt][2], ah[mt][3], ad);
            ldm4(al[mt][0], al[mt][1], al[mt][2], al[mt][3], ad + 5120 * 2);
        }
        uint32_t b1[4][2], b2[4][2];
#pragma unroll
        for (int p = 0; p < 2; p++) {
            int nr = (wid >> 2) * 32 + p * 16 + (lane & 7) + ((lane & 16) >> 1);
            int hc = ks * 16 + (lane & 8);
            uint32_t bd = smb + (uint32_t)(boff + nr * ROWP + hc) * 2;
            ldm4(b1[2*p][0], b1[2*p][1], b1[2*p+1][0], b1[2*p+1][1], bd);
            ldm4(b2[2*p][0], b2[2*p][1], b2[2*p+1][0], b2[2*p+1][1], bd + 2560 * 2);
        }
#pragma unroll
        for (int mt = 0; mt < 2; mt++)
#pragma unroll
            for (int nt = 0; nt < 4; nt++) {
                mma16816(A1[mt][nt], ah[mt], b1[nt]);
                mma16816(A1[mt][nt], al[mt], b1[nt]);
                mma16816(A2[mt][nt], ah[mt], b2[nt]);
                mma16816(A2[mt][nt], al[mt], b2[nt]);
            }
    }
}

__device__ __forceinline__ void ldgB1(const float* __restrict__ w1, const float* __restrict__ w2,
                                      int k0, int tid, float4 (&r1)[2], float4 (&r2)[2]) {
#pragma unroll
    for (int j = 0; j < 2; j++) {
        int w = tid + (j << 8); int r = w >> 3, cc = w & 7;
        r1[j] = *(const float4*)(w1 + (size_t)r * DIM + k0 + cc * 4);
        r2[j] = *(const float4*)(w2 + (size_t)r * DIM + k0 + cc * 4);
    }
}
__device__ __forceinline__ void stsB1(uint16_t* sm16, int bst, int tid,
                                      const float4 (&r1)[2], const float4 (&r2)[2]) {
    int boff = A_TOT + bst * B1_STG;
#pragma unroll
    for (int j = 0; j < 2; j++) {
        int w = tid + (j << 8); int r = w >> 3, cc = w & 7;
        *(ull*)(sm16 + boff + r * ROWP + cc * 4) = f4toh4(r1[j]);
        *(ull*)(sm16 + boff + 2560 + r * ROWP + cc * 4) = f4toh4(r2[j]);
    }
}

__global__ void __launch_bounds__(256, 1) k_ffn1(const float* __restrict__ W1,
                                                 const float* __restrict__ W2) {
    int e = blockIdx.z;
    int rbeg = g_off[e], rend = g_off[e + 1];
    int row0 = rbeg + blockIdx.y * 128;
    if (row0 >= rend) return;
    int n0 = blockIdx.x * 64;

    extern __shared__ __align__(16) uint16_t sm16[];
    __shared__ int s_tok[128];
    int tid = threadIdx.x, wid = tid >> 5, lane = tid & 31;
    uint32_t smb = s2u(sm16);

    if (tid < 128) {
        int rr = row0 + tid;
        s_tok[tid] = g_tok[rr < rend ? rr : rbeg];
    }
    __syncthreads();

    const float* w1 = W1 + ((size_t)e * HID + n0) * DIM;
    const float* w2 = W2 + ((size_t)e * HID + n0) * DIM;

    float acc1[2][4][4], acc2[2][4][4];
#pragma unroll
    for (int a = 0; a < 2; a++)
#pragma unroll
        for (int b = 0; b < 4; b++)
#pragma unroll
            for (int c = 0; c < 4; c++) { acc1[a][b][c] = 0.f; acc2[a][b][c] = 0.f; }

    const int NC = DIM / 32;  // 32
    cpA(smb, 0 * A_STG, tid, s_tok, g_xh, g_xl, DIM, 0);  CP_COMMIT();
    cpA(smb, 1 * A_STG, tid, s_tok, g_xh, g_xl, DIM, 32); CP_COMMIT();
    cpA(smb, 2 * A_STG, tid, s_tok, g_xh, g_xl, DIM, 64); CP_COMMIT();
    float4 r1[2], r2[2];
    ldgB1(w1, w2, 0, tid, r1, r2);
    stsB1(sm16, 0, tid, r1, r2);
    ldgB1(w1, w2, 32, tid, r1, r2);

    for (int c = 0; c < NC; c++) {
        CP_WAIT2();
        __syncthreads();
        if (c + 3 < NC) cpA(smb, ((c + 3) & 3) * A_STG, tid, s_tok, g_xh, g_xl, DIM, (c + 3) * 32);
        CP_COMMIT();
        if (c + 1 < NC) stsB1(sm16, (c + 1) & 1, tid, r1, r2);
        if (c + 2 < NC) ldgB1(w1, w2, (c + 2) * 32, tid, r1, r2);
        comp1(smb, c & 3, c & 1, wid, lane, acc1, acc2);
    }

    // epilogue: silu(g)*u, split to fp16 hi/lo, planar store
    int wm = wid & 3, wn = wid >> 2;
#pragma unroll
    for (int mt = 0; mt < 2; mt++) {
        int rbse = row0 + wm * 32 + mt * 16 + (lane >> 2);
#pragma unroll
        for (int h2 = 0; h2 < 2; h2++) {
            int row = rbse + h2 * 8;
            if (row >= rend) continue;
            int colb = n0 + wn * 32 + (lane & 3) * 2;
            __half* hh = g_Hh + (size_t)row * HID + colb;
            __half* hl = g_Hl + (size_t)row * HID + colb;
#pragma unroll
            for (int nt = 0; nt < 4; nt++) {
                float g0 = acc1[mt][nt][h2 * 2 + 0], u0 = acc2[mt][nt][h2 * 2 + 0];
                float g1 = acc1[mt][nt][h2 * 2 + 1], u1 = acc2[mt][nt][h2 * 2 + 1];
                float hv0 = g0 * u0 / (1.f + expf(-g0));
                float hv1 = g1 * u1 / (1.f + expf(-g1));
                unsigned ph = hpack(hv0, hv1);
                float f0 = __half2float(__ushort_as_half((unsigned short)(ph & 0xffff)));
                float f1 = __half2float(__ushort_as_half((unsigned short)(ph >> 16)));
                unsigned pl = hpack(hv0 - f0, hv1 - f1);
                *(unsigned*)(hh + nt * 8) = ph;
                *(unsigned*)(hl + nt * 8) = pl;
            }
        }
    }
}

// ---------------- GEMM2 ----------------
__device__ __forceinline__ void comp2(uint32_t smb, int ast, int bst, int wid, int lane,
                                      float (&A)[2][4][4]) {
    int aoff = ast * A_STG;
    int boff = A_TOT + bst * B2_STG;
#pragma unroll
    for (int ks = 0; ks < 2; ks++) {
        uint32_t ah[2][4], al[2][4];
#pragma unroll
        for (int mt = 0; mt < 2; mt++) {
            int row = (wid & 3) * 32 + mt * 16 + (lane & 15);
            int hc = ks * 16 + ((lane & 16) >> 1);
            uint32_t ad = smb + (uint32_t)(aoff + row * ROWP + hc) * 2;
            ldm4(ah[mt][0], ah[mt][1], ah[mt][2], ah[mt][3], ad);
            ldm4(al[mt][0], al[mt][1], al[mt][2], al[mt][3], ad + 5120 * 2);
        }
        uint32_t bb[4][2];
#pragma unroll
        for (int p = 0; p < 2; p++) {
            int nr = (wid >> 2) * 32 + p * 16 + (lane & 7) + ((lane & 16) >> 1);
            int hc = ks * 16 + (lane & 8);
            uint32_t bd = smb + (uint32_t)(boff + nr * ROWP + hc) * 2;
            ldm4(bb[2*p][0], bb[2*p][1], bb[2*p+1][0], bb[2*p+1][1], bd);
        }
#pragma unroll
        for (int mt = 0; mt < 2; mt++)
#pragma unroll
            for (int nt = 0; nt < 4; nt++) {
                mma16816(A[mt][nt], ah[mt], bb[nt]);
                mma16816(A[mt][nt], al[mt], bb[nt]);
            }
    }
}

__device__ __forceinline__ void ldgB2(const float* __restrict__ w3, int k0, int tid, float4 (&r3)[2]) {
#pragma unroll
    for (int j = 0; j < 2; j++) {
        int w = tid + (j << 8); int r = w >> 3, cc = w & 7;
        r3[j] = *(const float4*)(w3 + (size_t)r * HID + k0 + cc * 4);
    }
}
__device__ __forceinline__ void stsB2(uint16_t* sm16, int bst, int tid, const float4 (&r3)[2]) {
    int boff = A_TOT + bst * B2_STG;
#pragma unroll
    for (int j = 0; j < 2; j++) {
        int w = tid + (j << 8); int r = w >> 3, cc = w & 7;
        *(ull*)(sm16 + boff + r * ROWP + cc * 4) = f4toh4(r3[j]);
    }
}

__global__ void __launch_bounds__(256, 1) k_ffn2(const float* __restrict__ W3,
                                                 float* __restrict__ out) {
    int e = blockIdx.z;
    int rbeg = g_off[e], rend = g_off[e + 1];
    int row0 = rbeg + blockIdx.y * 128;
    if (row0 >= rend) return;
    int n0 = blockIdx.x * 64;

    extern __shared__ __align__(16) uint16_t sm16[];
    __shared__ int s_row[128];
    int tid = threadIdx.x, wid = tid >> 5, lane = tid & 31;
    uint32_t smb = s2u(sm16);

    if (tid < 128) {
        int rr = row0 + tid;
        s_row[tid] = (rr < rend) ? rr : rbeg;
    }
    __syncthreads();

    const float* w3 = W3 + ((size_t)e * DIM + n0) * HID;

    float acc[2][4][4];
#pragma unroll
    for (int a = 0; a < 2; a++)
#pragma unroll
        for (int b = 0; b < 4; b++)
#pragma unroll
            for (int c = 0; c < 4; c++) acc[a][b][c] = 0.f;

    const int NC = HID / 32;  // 88
    cpA(smb, 0 * A_STG, tid, s_row, g_Hh, g_Hl, HID, 0);  CP_COMMIT();
    cpA(smb, 1 * A_STG, tid, s_row, g_Hh, g_Hl, HID, 32); CP_COMMIT();
    cpA(smb, 2 * A_STG, tid, s_row, g_Hh, g_Hl, HID, 64); CP_COMMIT();
    float4 r3[2];
    ldgB2(w3, 0, tid, r3);
    stsB2(sm16, 0, tid, r3);
    ldgB2(w3, 32, tid, r3);

    for (int c = 0; c < NC; c++) {
        CP_WAIT2();
        __syncthreads();
        if (c + 3 < NC) cpA(smb, ((c + 3) & 3) * A_STG, tid, s_row, g_Hh, g_Hl, HID, (c + 3) * 32);
        CP_COMMIT();
        if (c + 1 < NC) stsB2(sm16, (c + 1) & 1, tid, r3);
        if (c + 2 < NC) ldgB2(w3, (c + 2) * 32, tid, r3);
        comp2(smb, c & 3, c & 1, wid, lane, acc);
    }

    // epilogue: scale by gate weight, atomicAdd into out (2 contributors -> deterministic)
    int wm = wid & 3, wn = wid >> 2;
#pragma unroll
    for (int mt = 0; mt < 2; mt++) {
        int rbse = row0 + wm * 32 + mt * 16 + (lane >> 2);
#pragma unroll
        for (int h2 = 0; h2 < 2; h2++) {
            int slot = rbse + h2 * 8;
            if (slot >= rend) continue;
            int tk = g_tok[slot];
            float wv = g_wslot[slot];
            float* ob = out + (size_t)tk * DIM + n0 + wn * 32 + (lane & 3) * 2;
#pragma unroll
            for (int nt = 0; nt < 4; nt++) {
                atomicAdd(ob + nt * 8,     acc[mt][nt][h2 * 2 + 0] * wv);
                atomicAdd(ob + nt * 8 + 1, acc[mt][nt][h2 * 2 + 1] * wv);
            }
        }
    }
}

// ---------------- launch ----------------
extern "C" void kernel_launch(void* const* d_in, const int* in_sizes, int n_in,
                              void* d_out, int out_size) {
    const float* x  = (const float*)d_in[0];
    const float* Wg = (const float*)d_in[1];
    const float* W1 = (const float*)d_in[2];
    const float* W2 = (const float*)d_in[3];
    const float* W3 = (const float*)d_in[4];
    float* out = (float*)d_out;

    cudaFuncSetAttribute(k_ffn1, cudaFuncAttributeMaxDynamicSharedMemorySize, SMEM1);
    cudaFuncSetAttribute(k_ffn2, cudaFuncAttributeMaxDynamicSharedMemorySize, SMEM2);

    k_zero_cnt<<<1, 32>>>();
    k_zero_out<<<(T_TOK * DIM / 4) / 256, 256>>>((float4*)out);
    k_gate<<<T_TOK / 8, 256>>>(x, Wg);
    k_scan<<<1, 1>>>();
    k_assign<<<T_TOK / 256, 256>>>();
    k_ffn1<<<dim3(HID / 64, 32, NEXP), 256, SMEM1>>>(W1, W2);
    k_ffn2<<<dim3(DIM / 64, 32, NEXP), 256, SMEM2>>>(W3, out);
}

// round 6
// speedup vs baseline: 1.2311x; 1.2311x over previous
#include <cuda_runtime.h>
#include <cuda_fp16.h>
#include <math.h>
#include <stdint.h>

#define T_TOK 4096
#define DIM   1024
#define NEXP  8
#define HID   2816
#define NSLOT (T_TOK*2)

typedef unsigned long long ull;

// ---------------- device scratch (static, no allocs) ----------------
__device__ __align__(16) __half g_xh[(size_t)T_TOK*DIM];
__device__ __align__(16) __half g_xl[(size_t)T_TOK*DIM];
__device__ __align__(16) __half g_Hh[(size_t)NSLOT*HID];
__device__ __align__(16) __half g_Hl[(size_t)NSLOT*HID];
__device__ int   g_tok[NSLOT];
__device__ float g_wslot[NSLOT];
__device__ int   g_te[NSLOT];
__device__ float g_tw[NSLOT];
__device__ int   g_cnt[NEXP];
__device__ int   g_off[NEXP + 1];
__device__ int   g_cur[NEXP];

// ---------------- helpers ----------------
__device__ __forceinline__ uint32_t s2u(const void* p) {
    uint32_t a;
    asm("{ .reg .u64 t; cvta.to.shared.u64 t, %1; cvt.u32.u64 %0, t; }" : "=r"(a) : "l"(p));
    return a;
}
__device__ __forceinline__ unsigned hpack(float lo_elem, float hi_elem) {
    unsigned r;
    asm("cvt.rn.f16x2.f32 %0, %1, %2;" : "=r"(r) : "f"(hi_elem), "f"(lo_elem));
    return r;
}
__device__ __forceinline__ ull f4toh4(float4 v) {
    unsigned p0 = hpack(v.x, v.y);
    unsigned p1 = hpack(v.z, v.w);
    return (ull)p0 | ((ull)p1 << 32);
}
__device__ __forceinline__ void ldm4(uint32_t& r0, uint32_t& r1, uint32_t& r2, uint32_t& r3, uint32_t a) {
    asm volatile("ldmatrix.sync.aligned.m8n8.x4.shared.b16 {%0,%1,%2,%3}, [%4];"
        : "=r"(r0), "=r"(r1), "=r"(r2), "=r"(r3) : "r"(a));
}
__device__ __forceinline__ void mma16816(float* c, const uint32_t* a, const uint32_t* b) {
    asm volatile("mma.sync.aligned.m16n8k16.row.col.f32.f16.f16.f32 "
        "{%0,%1,%2,%3}, {%4,%5,%6,%7}, {%8,%9}, {%0,%1,%2,%3};"
        : "+f"(c[0]), "+f"(c[1]), "+f"(c[2]), "+f"(c[3])
        : "r"(a[0]), "r"(a[1]), "r"(a[2]), "r"(a[3]), "r"(b[0]), "r"(b[1]));
}
__device__ __forceinline__ void cpa16(uint32_t dst, const void* src) {
    asm volatile("cp.async.cg.shared.global [%0], [%1], 16;" :: "r"(dst), "l"(src) : "memory");
}
#define CP_COMMIT() asm volatile("cp.async.commit_group;" ::: "memory")
#define CP_WAIT2()  asm volatile("cp.async.wait_group 2;" ::: "memory")

// smem geometry (halves): rows padded to 40 (k32 + 8)
#define ROWP   40
#define A_STG  10240                 // Ah(5120) + Al(5120) per stage (128 rows)
#define A_TOT  (4*A_STG)
#define B1_STG 5120                  // B1(2560) + B2(2560) (64 rows each)
#define B2_STG 2560                  // B(2560)
#define SMEM1  ((A_TOT + 2*B1_STG)*2)   // 102400
#define SMEM2  ((A_TOT + 2*B2_STG)*2)   // 92160

// ---------------- small kernels ----------------
__global__ void k_zero_cnt() { if (threadIdx.x < NEXP) g_cnt[threadIdx.x] = 0; }

__global__ void k_zero_out(float4* o) {
    o[blockIdx.x * 256 + threadIdx.x] = make_float4(0.f, 0.f, 0.f, 0.f);
}

// gating + split x into planar fp16 hi/lo
__global__ void k_gate(const float* __restrict__ x, const float* __restrict__ Wg) {
    int t = (blockIdx.x * blockDim.x + threadIdx.x) >> 5;
    int lane = threadIdx.x & 31;
    if (t >= T_TOK) return;
    const float4* xr = reinterpret_cast<const float4*>(x + (size_t)t * DIM);
    float s[NEXP];
#pragma unroll
    for (int e = 0; e < NEXP; e++) s[e] = 0.f;
    for (int i = lane; i < DIM / 4; i += 32) {
        float4 xv = xr[i];
#pragma unroll
        for (int e = 0; e < NEXP; e++) {
            float4 wv = reinterpret_cast<const float4*>(Wg + (size_t)e * DIM)[i];
            s[e] += xv.x * wv.x + xv.y * wv.y + xv.z * wv.z + xv.w * wv.w;
        }
        unsigned h01 = hpack(xv.x, xv.y);
        unsigned h23 = hpack(xv.z, xv.w);
        float f0 = __half2float(__ushort_as_half((unsigned short)(h01 & 0xffff)));
        float f1 = __half2float(__ushort_as_half((unsigned short)(h01 >> 16)));
        float f2 = __half2float(__ushort_as_half((unsigned short)(h23 & 0xffff)));
        float f3 = __half2float(__ushort_as_half((unsigned short)(h23 >> 16)));
        unsigned l01 = hpack(xv.x - f0, xv.y - f1);
        unsigned l23 = hpack(xv.z - f2, xv.w - f3);
        *(uint2*)(g_xh + (size_t)t * DIM + i * 4) = make_uint2(h01, h23);
        *(uint2*)(g_xl + (size_t)t * DIM + i * 4) = make_uint2(l01, l23);
    }
#pragma unroll
    for (int e = 0; e < NEXP; e++) {
#pragma unroll
        for (int o = 16; o > 0; o >>= 1) s[e] += __shfl_xor_sync(0xffffffffu, s[e], o);
    }
    if (lane == 0) {
        int b0 = 0; float v0 = s[0];
#pragma unroll
        for (int e = 1; e < NEXP; e++) if (s[e] > v0) { v0 = s[e]; b0 = e; }
        int b1 = -1; float v1 = -3.4e38f;
#pragma unroll
        for (int e = 0; e < NEXP; e++) if (e != b0 && s[e] > v1) { v1 = s[e]; b1 = e; }
        g_te[t * 2 + 0] = b0;  g_te[t * 2 + 1] = b1;
        g_tw[t * 2 + 0] = v0;  g_tw[t * 2 + 1] = v1;
        atomicAdd(&g_cnt[b0], 1);
        atomicAdd(&g_cnt[b1], 1);
    }
}

__global__ void k_scan() {
    int o = 0;
    for (int e = 0; e < NEXP; e++) { g_off[e] = o; g_cur[e] = o; o += g_cnt[e]; }
    g_off[NEXP] = o;
}

__global__ void k_assign() {
    int t = blockIdx.x * blockDim.x + threadIdx.x;
    if (t >= T_TOK) return;
#pragma unroll
    for (int k = 0; k < 2; k++) {
        int e = g_te[t * 2 + k];
        int pos = atomicAdd(&g_cur[e], 1);
        g_tok[pos] = t;
        g_wslot[pos] = g_tw[t * 2 + k];
    }
}

// ---------------- A staging: 1 cp.async per plane per thread (512 threads) ----------------
__device__ __forceinline__ void cpA(uint32_t smb, int soff, int tid, const int* s_idx,
                                    const __half* __restrict__ ah, const __half* __restrict__ al,
                                    int rowstride, int k0) {
    int r = tid >> 2, g = tid & 3;
    size_t so = (size_t)s_idx[r] * rowstride + k0 + g * 8;
    uint32_t d = smb + (uint32_t)(soff + r * ROWP + g * 8) * 2;
    cpa16(d, ah + so);
    cpa16(d + 5120 * 2, al + so);
}

// ---------------- GEMM1 (M=128, N=64, 16 warps, warp tile 32x16) ----------------
__device__ __forceinline__ void comp1(uint32_t smb, int ast, int bst, int wid, int lane,
                                      float (&A1)[2][2][4], float (&A2)[2][2][4]) {
    int aoff = ast * A_STG;
    int boff = A_TOT + bst * B1_STG;
#pragma unroll
    for (int ks = 0; ks < 2; ks++) {
        uint32_t ah[2][4], al[2][4];
#pragma unroll
        for (int mt = 0; mt < 2; mt++) {
            int row = (wid & 3) * 32 + mt * 16 + (lane & 15);
            int hc = ks * 16 + ((lane & 16) >> 1);
            uint32_t ad = smb + (uint32_t)(aoff + row * ROWP + hc) * 2;
            ldm4(ah[mt][0], ah[mt][1], ah[mt][2], ah[mt][3], ad);
            ldm4(al[mt][0], al[mt][1], al[mt][2], al[mt][3], ad + 5120 * 2);
        }
        uint32_t b1[2][2], b2[2][2];
        {
            int nr = (wid >> 2) * 16 + (lane & 7) + ((lane & 16) >> 1);
            int hc = ks * 16 + (lane & 8);
            uint32_t bd = smb + (uint32_t)(boff + nr * ROWP + hc) * 2;
            ldm4(b1[0][0], b1[0][1], b1[1][0], b1[1][1], bd);
            ldm4(b2[0][0], b2[0][1], b2[1][0], b2[1][1], bd + 2560 * 2);
        }
#pragma unroll
        for (int mt = 0; mt < 2; mt++)
#pragma unroll
            for (int nt = 0; nt < 2; nt++) {
                mma16816(A1[mt][nt], ah[mt], b1[nt]);
                mma16816(A1[mt][nt], al[mt], b1[nt]);
                mma16816(A2[mt][nt], ah[mt], b2[nt]);
                mma16816(A2[mt][nt], al[mt], b2[nt]);
            }
    }
}

__device__ __forceinline__ void ldgB1(const float* __restrict__ w1, const float* __restrict__ w2,
                                      int k0, int tid, float4& r1, float4& r2) {
    int r = tid >> 3, cc = tid & 7;
    r1 = *(const float4*)(w1 + (size_t)r * DIM + k0 + cc * 4);
    r2 = *(const float4*)(w2 + (size_t)r * DIM + k0 + cc * 4);
}
__device__ __forceinline__ void stsB1(uint16_t* sm16, int bst, int tid,
                                      const float4& r1, const float4& r2) {
    int boff = A_TOT + bst * B1_STG;
    int r = tid >> 3, cc = tid & 7;
    *(ull*)(sm16 + boff + r * ROWP + cc * 4) = f4toh4(r1);
    *(ull*)(sm16 + boff + 2560 + r * ROWP + cc * 4) = f4toh4(r2);
}

__global__ void __launch_bounds__(512, 1) k_ffn1(const float* __restrict__ W1,
                                                 const float* __restrict__ W2) {
    int e = blockIdx.z;
    int rbeg = g_off[e], rend = g_off[e + 1];
    int row0 = rbeg + blockIdx.y * 128;
    if (row0 >= rend) return;
    int n0 = blockIdx.x * 64;

    extern __shared__ __align__(16) uint16_t sm16[];
    __shared__ int s_tok[128];
    int tid = threadIdx.x, wid = tid >> 5, lane = tid & 31;
    uint32_t smb = s2u(sm16);

    if (tid < 128) {
        int rr = row0 + tid;
        s_tok[tid] = g_tok[rr < rend ? rr : rbeg];
    }
    __syncthreads();

    const float* w1 = W1 + ((size_t)e * HID + n0) * DIM;
    const float* w2 = W2 + ((size_t)e * HID + n0) * DIM;

    float acc1[2][2][4], acc2[2][2][4];
#pragma unroll
    for (int a = 0; a < 2; a++)
#pragma unroll
        for (int b = 0; b < 2; b++)
#pragma unroll
            for (int c = 0; c < 4; c++) { acc1[a][b][c] = 0.f; acc2[a][b][c] = 0.f; }

    const int NC = DIM / 32;  // 32
    cpA(smb, 0 * A_STG, tid, s_tok, g_xh, g_xl, DIM, 0);  CP_COMMIT();
    cpA(smb, 1 * A_STG, tid, s_tok, g_xh, g_xl, DIM, 32); CP_COMMIT();
    cpA(smb, 2 * A_STG, tid, s_tok, g_xh, g_xl, DIM, 64); CP_COMMIT();
    float4 r1, r2;
    ldgB1(w1, w2, 0, tid, r1, r2);
    stsB1(sm16, 0, tid, r1, r2);
    ldgB1(w1, w2, 32, tid, r1, r2);

    for (int c = 0; c < NC; c++) {
        CP_WAIT2();
        __syncthreads();
        if (c + 3 < NC) cpA(smb, ((c + 3) & 3) * A_STG, tid, s_tok, g_xh, g_xl, DIM, (c + 3) * 32);
        CP_COMMIT();
        if (c + 1 < NC) stsB1(sm16, (c + 1) & 1, tid, r1, r2);
        if (c + 2 < NC) ldgB1(w1, w2, (c + 2) * 32, tid, r1, r2);
        comp1(smb, c & 3, c & 1, wid, lane, acc1, acc2);
    }

    // epilogue: silu(g)*u, split fp16 hi/lo, planar store
    int wr = wid & 3, wc = wid >> 2;
#pragma unroll
    for (int mt = 0; mt < 2; mt++) {
        int rbse = row0 + wr * 32 + mt * 16 + (lane >> 2);
#pragma unroll
        for (int h2 = 0; h2 < 2; h2++) {
            int row = rbse + h2 * 8;
            if (row >= rend) continue;
            int colb = n0 + wc * 16 + (lane & 3) * 2;
            __half* hh = g_Hh + (size_t)row * HID + colb;
            __half* hl = g_Hl + (size_t)row * HID + colb;
#pragma unroll
            for (int nt = 0; nt < 2; nt++) {
                float g0 = acc1[mt][nt][h2 * 2 + 0], u0 = acc2[mt][nt][h2 * 2 + 0];
                float g1 = acc1[mt][nt][h2 * 2 + 1], u1 = acc2[mt][nt][h2 * 2 + 1];
                float hv0 = g0 * u0 / (1.f + expf(-g0));
                float hv1 = g1 * u1 / (1.f + expf(-g1));
                unsigned ph = hpack(hv0, hv1);
                float f0 = __half2float(__ushort_as_half((unsigned short)(ph & 0xffff)));
                float f1 = __half2float(__ushort_as_half((unsigned short)(ph >> 16)));
                unsigned pl = hpack(hv0 - f0, hv1 - f1);
                *(unsigned*)(hh + nt * 8) = ph;
                *(unsigned*)(hl + nt * 8) = pl;
            }
        }
    }
}

// ---------------- GEMM2 (M=128, N=64, 16 warps) ----------------
__device__ __forceinline__ void comp2(uint32_t smb, int ast, int bst, int wid, int lane,
                                      float (&A)[2][2][4]) {
    int aoff = ast * A_STG;
    int boff = A_TOT + bst * B2_STG;
#pragma unroll
    for (int ks = 0; ks < 2; ks++) {
        uint32_t ah[2][4], al[2][4];
#pragma unroll
        for (int mt = 0; mt < 2; mt++) {
            int row = (wid & 3) * 32 + mt * 16 + (lane & 15);
            int hc = ks * 16 + ((lane & 16) >> 1);
            uint32_t ad = smb + (uint32_t)(aoff + row * ROWP + hc) * 2;
            ldm4(ah[mt][0], ah[mt][1], ah[mt][2], ah[mt][3], ad);
            ldm4(al[mt][0], al[mt][1], al[mt][2], al[mt][3], ad + 5120 * 2);
        }
        uint32_t bb[2][2];
        {
            int nr = (wid >> 2) * 16 + (lane & 7) + ((lane & 16) >> 1);
            int hc = ks * 16 + (lane & 8);
            uint32_t bd = smb + (uint32_t)(boff + nr * ROWP + hc) * 2;
            ldm4(bb[0][0], bb[0][1], bb[1][0], bb[1][1], bd);
        }
#pragma unroll
        for (int mt = 0; mt < 2; mt++)
#pragma unroll
            for (int nt = 0; nt < 2; nt++) {
                mma16816(A[mt][nt], ah[mt], bb[nt]);
                mma16816(A[mt][nt], al[mt], bb[nt]);
            }
    }
}

__device__ __forceinline__ void ldgB2(const float* __restrict__ w3, int k0, int tid, float4& r3) {
    int r = tid >> 3, cc = tid & 7;
    r3 = *(const float4*)(w3 + (size_t)r * HID + k0 + cc * 4);
}
__device__ __forceinline__ void stsB2(uint16_t* sm16, int bst, int tid, const float4& r3) {
    int boff = A_TOT + bst * B2_STG;
    int r = tid >> 3, cc = tid & 7;
    *(ull*)(sm16 + boff + r * ROWP + cc * 4) = f4toh4(r3);
}

__global__ void __launch_bounds__(512, 1) k_ffn2(const float* __restrict__ W3,
                                                 float* __restrict__ out) {
    int e = blockIdx.z;
    int rbeg = g_off[e], rend = g_off[e + 1];
    int row0 = rbeg + blockIdx.y * 128;
    if (row0 >= rend) return;
    int n0 = blockIdx.x * 64;

    extern __shared__ __align__(16) uint16_t sm16[];
    __shared__ int s_row[128];
    int tid = threadIdx.x, wid = tid >> 5, lane = tid & 31;
    uint32_t smb = s2u(sm16);

    if (tid < 128) {
        int rr = row0 + tid;
        s_row[tid] = (rr < rend) ? rr : rbeg;
    }
    __syncthreads();

    const float* w3 = W3 + ((size_t)e * DIM + n0) * HID;

    float acc[2][2][4];
#pragma unroll
    for (int a = 0; a < 2; a++)
#pragma unroll
        for (int b = 0; b < 2; b++)
#pragma unroll
            for (int c = 0; c < 4; c++) acc[a][b][c] = 0.f;

    const int NC = HID / 32;  // 88
    cpA(smb, 0 * A_STG, tid, s_row, g_Hh, g_Hl, HID, 0);  CP_COMMIT();
    cpA(smb, 1 * A_STG, tid, s_row, g_Hh, g_Hl, HID, 32); CP_COMMIT();
    cpA(smb, 2 * A_STG, tid, s_row, g_Hh, g_Hl, HID, 64); CP_COMMIT();
    float4 r3;
    ldgB2(w3, 0, tid, r3);
    stsB2(sm16, 0, tid, r3);
    ldgB2(w3, 32, tid, r3);

    for (int c = 0; c < NC; c++) {
        CP_WAIT2();
        __syncthreads();
        if (c + 3 < NC) cpA(smb, ((c + 3) & 3) * A_STG, tid, s_row, g_Hh, g_Hl, HID, (c + 3) * 32);
        CP_COMMIT();
        if (c + 1 < NC) stsB2(sm16, (c + 1) & 1, tid, r3);
        if (c + 2 < NC) ldgB2(w3, (c + 2) * 32, tid, r3);
        comp2(smb, c & 3, c & 1, wid, lane, acc);
    }

    // epilogue: scale by gate weight, atomicAdd (2 contributors -> deterministic)
    int wr = wid & 3, wc = wid >> 2;
#pragma unroll
    for (int mt = 0; mt < 2; mt++) {
        int rbse = row0 + wr * 32 + mt * 16 + (lane >> 2);
#pragma unroll
        for (int h2 = 0; h2 < 2; h2++) {
            int slot = rbse + h2 * 8;
            if (slot >= rend) continue;
            int tk = g_tok[slot];
            float wv = g_wslot[slot];
            float* ob = out + (size_t)tk * DIM + n0 + wc * 16 + (lane & 3) * 2;
#pragma unroll
            for (int nt = 0; nt < 2; nt++) {
                atomicAdd(ob + nt * 8,     acc[mt][nt][h2 * 2 + 0] * wv);
                atomicAdd(ob + nt * 8 + 1, acc[mt][nt][h2 * 2 + 1] * wv);
            }
        }
    }
}

// ---------------- launch ----------------
extern "C" void kernel_launch(void* const* d_in, const int* in_sizes, int n_in,
                              void* d_out, int out_size) {
    const float* x  = (const float*)d_in[0];
    const float* Wg = (const float*)d_in[1];
    const float* W1 = (const float*)d_in[2];
    const float* W2 = (const float*)d_in[3];
    const float* W3 = (const float*)d_in[4];
    float* out = (float*)d_out;

    cudaFuncSetAttribute(k_ffn1, cudaFuncAttributeMaxDynamicSharedMemorySize, SMEM1);
    cudaFuncSetAttribute(k_ffn2, cudaFuncAttributeMaxDynamicSharedMemorySize, SMEM2);

    k_zero_cnt<<<1, 32>>>();
    k_zero_out<<<(T_TOK * DIM / 4) / 256, 256>>>((float4*)out);
    k_gate<<<T_TOK / 8, 256>>>(x, Wg);
    k_scan<<<1, 1>>>();
    k_assign<<<T_TOK / 256, 256>>>();
    k_ffn1<<<dim3(HID / 64, 32, NEXP), 512, SMEM1>>>(W1, W2);
    k_ffn2<<<dim3(DIM / 64, 32, NEXP), 512, SMEM2>>>(W3, out);
}

// round 8
// speedup vs baseline: 1.6207x; 1.3165x over previous
#include <cuda_runtime.h>
#include <cuda_fp16.h>
#include <math.h>
#include <stdint.h>

#define T_TOK 4096
#define DIM   1024
#define NEXP  8
#define HID   2816
#define NSLOT (T_TOK*2)

typedef unsigned long long ull;

// ---------------- device scratch (static, no allocs) ----------------
__device__ __align__(16) __half g_xh[(size_t)T_TOK*DIM];
__device__ __align__(16) __half g_xl[(size_t)T_TOK*DIM];
__device__ __align__(16) __half g_Hh[(size_t)NSLOT*HID];
__device__ __align__(16) __half g_Hl[(size_t)NSLOT*HID];
__device__ int   g_tok[NSLOT];
__device__ float g_wslot[NSLOT];
__device__ int   g_te[NSLOT];
__device__ float g_tw[NSLOT];
__device__ int   g_cnt[NEXP];
__device__ int   g_off[NEXP + 1];
__device__ int   g_cur[NEXP];

// ---------------- helpers ----------------
__device__ __forceinline__ uint32_t s2u(const void* p) {
    uint32_t a;
    asm("{ .reg .u64 t; cvta.to.shared.u64 t, %1; cvt.u32.u64 %0, t; }" : "=r"(a) : "l"(p));
    return a;
}
__device__ __forceinline__ unsigned hpack(float lo_elem, float hi_elem) {
    unsigned r;
    asm("cvt.rn.f16x2.f32 %0, %1, %2;" : "=r"(r) : "f"(hi_elem), "f"(lo_elem));
    return r;
}
__device__ __forceinline__ ull f4toh4(float4 v) {
    unsigned p0 = hpack(v.x, v.y);
    unsigned p1 = hpack(v.z, v.w);
    return (ull)p0 | ((ull)p1 << 32);
}
__device__ __forceinline__ void ldm4(uint32_t& r0, uint32_t& r1, uint32_t& r2, uint32_t& r3, uint32_t a) {
    asm volatile("ldmatrix.sync.aligned.m8n8.x4.shared.b16 {%0,%1,%2,%3}, [%4];"
        : "=r"(r0), "=r"(r1), "=r"(r2), "=r"(r3) : "r"(a));
}
__device__ __forceinline__ void mma16816(float* c, const uint32_t* a, const uint32_t* b) {
    asm volatile("mma.sync.aligned.m16n8k16.row.col.f32.f16.f16.f32 "
        "{%0,%1,%2,%3}, {%4,%5,%6,%7}, {%8,%9}, {%0,%1,%2,%3};"
        : "+f"(c[0]), "+f"(c[1]), "+f"(c[2]), "+f"(c[3])
        : "r"(a[0]), "r"(a[1]), "r"(a[2]), "r"(a[3]), "r"(b[0]), "r"(b[1]));
}
__device__ __forceinline__ void cpa16(uint32_t dst, const void* src) {
    asm volatile("cp.async.cg.shared.global [%0], [%1], 16;" :: "r"(dst), "l"(src) : "memory");
}
#define CP_COMMIT() asm volatile("cp.async.commit_group;" ::: "memory")
#define CP_WAIT2()  asm volatile("cp.async.wait_group 2;" ::: "memory")

// smem geometry (halves): rows padded to 40 (k32 + 8)
#define ROWP   40
#define A_STG  10240                 // Ah(5120)+Al(5120) per stage (128 rows)
#define A_TOT  (4*A_STG)
#define B1_STG 10240                 // B1(5120)+B2(5120), 128 N-rows each
#define B2_STG 5120                  // B(5120), 128 N-rows
#define SMEM1  ((A_TOT + 2*B1_STG)*2)   // 122880
#define SMEM2  ((A_TOT + 2*B2_STG)*2)   // 102400

// ---------------- small kernels ----------------
__global__ void k_zero_cnt() { if (threadIdx.x < NEXP) g_cnt[threadIdx.x] = 0; }

__global__ void k_zero_out(float4* o) {
    o[blockIdx.x * 256 + threadIdx.x] = make_float4(0.f, 0.f, 0.f, 0.f);
}

// gating + split x into planar fp16 hi/lo
__global__ void k_gate(const float* __restrict__ x, const float* __restrict__ Wg) {
    int t = (blockIdx.x * blockDim.x + threadIdx.x) >> 5;
    int lane = threadIdx.x & 31;
    if (t >= T_TOK) return;
    const float4* xr = reinterpret_cast<const float4*>(x + (size_t)t * DIM);
    float s[NEXP];
#pragma unroll
    for (int e = 0; e < NEXP; e++) s[e] = 0.f;
    for (int i = lane; i < DIM / 4; i += 32) {
        float4 xv = xr[i];
#pragma unroll
        for (int e = 0; e < NEXP; e++) {
            float4 wv = reinterpret_cast<const float4*>(Wg + (size_t)e * DIM)[i];
            s[e] += xv.x * wv.x + xv.y * wv.y + xv.z * wv.z + xv.w * wv.w;
        }
        unsigned h01 = hpack(xv.x, xv.y);
        unsigned h23 = hpack(xv.z, xv.w);
        float f0 = __half2float(__ushort_as_half((unsigned short)(h01 & 0xffff)));
        float f1 = __half2float(__ushort_as_half((unsigned short)(h01 >> 16)));
        float f2 = __half2float(__ushort_as_half((unsigned short)(h23 & 0xffff)));
        float f3 = __half2float(__ushort_as_half((unsigned short)(h23 >> 16)));
        unsigned l01 = hpack(xv.x - f0, xv.y - f1);
        unsigned l23 = hpack(xv.z - f2, xv.w - f3);
        *(uint2*)(g_xh + (size_t)t * DIM + i * 4) = make_uint2(h01, h23);
        *(uint2*)(g_xl + (size_t)t * DIM + i * 4) = make_uint2(l01, l23);
    }
#pragma unroll
    for (int e = 0; e < NEXP; e++) {
#pragma unroll
        for (int o = 16; o > 0; o >>= 1) s[e] += __shfl_xor_sync(0xffffffffu, s[e], o);
    }
    if (lane == 0) {
        int b0 = 0; float v0 = s[0];
#pragma unroll
        for (int e = 1; e < NEXP; e++) if (s[e] > v0) { v0 = s[e]; b0 = e; }
        int b1 = -1; float v1 = -3.4e38f;
#pragma unroll
        for (int e = 0; e < NEXP; e++) if (e != b0 && s[e] > v1) { v1 = s[e]; b1 = e; }
        g_te[t * 2 + 0] = b0;  g_te[t * 2 + 1] = b1;
        g_tw[t * 2 + 0] = v0;  g_tw[t * 2 + 1] = v1;
        atomicAdd(&g_cnt[b0], 1);
        atomicAdd(&g_cnt[b1], 1);
    }
}

__global__ void k_scan() {
    int o = 0;
    for (int e = 0; e < NEXP; e++) { g_off[e] = o; g_cur[e] = o; o += g_cnt[e]; }
    g_off[NEXP] = o;
}

__global__ void k_assign() {
    int t = blockIdx.x * blockDim.x + threadIdx.x;
    if (t >= T_TOK) return;
#pragma unroll
    for (int k = 0; k < 2; k++) {
        int e = g_te[t * 2 + k];
        int pos = atomicAdd(&g_cur[e], 1);
        g_tok[pos] = t;
        g_wslot[pos] = g_tw[t * 2 + k];
    }
}

// ---------------- A staging: 1 cp.async per plane per thread (512 threads) ----------------
__device__ __forceinline__ void cpA(uint32_t smb, int soff, int tid, const int* s_idx,
                                    const __half* __restrict__ ah, const __half* __restrict__ al,
                                    int rowstride, int k0) {
    int r = tid >> 2, g = tid & 3;
    size_t so = (size_t)s_idx[r] * rowstride + k0 + g * 8;
    uint32_t d = smb + (uint32_t)(soff + r * ROWP + g * 8) * 2;
    cpa16(d, ah + so);
    cpa16(d + 5120 * 2, al + so);
}

// ---------------- GEMM1 (M=128, N=128, 16 warps, warp tile 32x32) ----------------
__device__ __forceinline__ void comp1(uint32_t smb, int ast, int bst, int wid, int lane,
                                      float (&A1)[2][4][4], float (&A2)[2][4][4]) {
    int aoff = ast * A_STG;
    int boff = A_TOT + bst * B1_STG;
#pragma unroll
    for (int ks = 0; ks < 2; ks++) {
        uint32_t ah[2][4], al[2][4];
#pragma unroll
        for (int mt = 0; mt < 2; mt++) {
            int row = (wid & 3) * 32 + mt * 16 + (lane & 15);
            int hc = ks * 16 + ((lane & 16) >> 1);
            uint32_t ad = smb + (uint32_t)(aoff + row * ROWP + hc) * 2;
            ldm4(ah[mt][0], ah[mt][1], ah[mt][2], ah[mt][3], ad);
            ldm4(al[mt][0], al[mt][1], al[mt][2], al[mt][3], ad + 5120 * 2);
        }
        uint32_t b1[4][2], b2[4][2];
#pragma unroll
        for (int p = 0; p < 2; p++) {
            int nr = (wid >> 2) * 32 + p * 16 + (lane & 7) + ((lane & 16) >> 1);
            int hc = ks * 16 + (lane & 8);
            uint32_t bd = smb + (uint32_t)(boff + nr * ROWP + hc) * 2;
            ldm4(b1[2*p][0], b1[2*p][1], b1[2*p+1][0], b1[2*p+1][1], bd);
            ldm4(b2[2*p][0], b2[2*p][1], b2[2*p+1][0], b2[2*p+1][1], bd + 5120 * 2);
        }
        // term-major: consecutive mma touch different accumulators
#pragma unroll
        for (int mt = 0; mt < 2; mt++)
#pragma unroll
            for (int nt = 0; nt < 4; nt++) {
                mma16816(A1[mt][nt], ah[mt], b1[nt]);
                mma16816(A2[mt][nt], ah[mt], b2[nt]);
            }
#pragma unroll
        for (int mt = 0; mt < 2; mt++)
#pragma unroll
            for (int nt = 0; nt < 4; nt++) {
                mma16816(A1[mt][nt], al[mt], b1[nt]);
                mma16816(A2[mt][nt], al[mt], b2[nt]);
            }
    }
}

__device__ __forceinline__ void ldgB1(const float* __restrict__ w1, const float* __restrict__ w2,
                                      int k0, int tid, float4 (&r1)[2], float4 (&r2)[2]) {
#pragma unroll
    for (int j = 0; j < 2; j++) {
        int idx = tid + (j << 9); int r = idx >> 3, cc = idx & 7;
        r1[j] = *(const float4*)(w1 + (size_t)r * DIM + k0 + cc * 4);
        r2[j] = *(const float4*)(w2 + (size_t)r * DIM + k0 + cc * 4);
    }
}
__device__ __forceinline__ void stsB1(uint16_t* sm16, int bst, int tid,
                                      const float4 (&r1)[2], const float4 (&r2)[2]) {
    int boff = A_TOT + bst * B1_STG;
#pragma unroll
    for (int j = 0; j < 2; j++) {
        int idx = tid + (j << 9); int r = idx >> 3, cc = idx & 7;
        *(ull*)(sm16 + boff + r * ROWP + cc * 4) = f4toh4(r1[j]);
        *(ull*)(sm16 + boff + 5120 + r * ROWP + cc * 4) = f4toh4(r2[j]);
    }
}

__global__ void __launch_bounds__(512, 1) k_ffn1(const float* __restrict__ W1,
                                                 const float* __restrict__ W2) {
    int e = blockIdx.z;
    int rbeg = g_off[e], rend = g_off[e + 1];
    int row0 = rbeg + blockIdx.y * 128;
    if (row0 >= rend) return;
    int n0 = blockIdx.x * 128;

    extern __shared__ __align__(16) uint16_t sm16[];
    __shared__ int s_tok[128];
    int tid = threadIdx.x, wid = tid >> 5, lane = tid & 31;
    uint32_t smb = s2u(sm16);

    if (tid < 128) {
        int rr = row0 + tid;
        s_tok[tid] = g_tok[rr < rend ? rr : rbeg];
    }
    __syncthreads();

    const float* w1 = W1 + ((size_t)e * HID + n0) * DIM;
    const float* w2 = W2 + ((size_t)e * HID + n0) * DIM;

    float acc1[2][4][4], acc2[2][4][4];
#pragma unroll
    for (int a = 0; a < 2; a++)
#pragma unroll
        for (int b = 0; b < 4; b++)
#pragma unroll
            for (int c = 0; c < 4; c++) { acc1[a][b][c] = 0.f; acc2[a][b][c] = 0.f; }

    const int NC = DIM / 32;  // 32
    cpA(smb, 0 * A_STG, tid, s_tok, g_xh, g_xl, DIM, 0);  CP_COMMIT();
    cpA(smb, 1 * A_STG, tid, s_tok, g_xh, g_xl, DIM, 32); CP_COMMIT();
    cpA(smb, 2 * A_STG, tid, s_tok, g_xh, g_xl, DIM, 64); CP_COMMIT();
    float4 r1[2], r2[2];
    ldgB1(w1, w2, 0, tid, r1, r2);
    stsB1(sm16, 0, tid, r1, r2);
    ldgB1(w1, w2, 32, tid, r1, r2);

    for (int c = 0; c < NC; c++) {
        CP_WAIT2();
        __syncthreads();
        if (c + 3 < NC) cpA(smb, ((c + 3) & 3) * A_STG, tid, s_tok, g_xh, g_xl, DIM, (c + 3) * 32);
        CP_COMMIT();
        if (c + 1 < NC) stsB1(sm16, (c + 1) & 1, tid, r1, r2);
        if (c + 2 < NC) ldgB1(w1, w2, (c + 2) * 32, tid, r1, r2);
        comp1(smb, c & 3, c & 1, wid, lane, acc1, acc2);
    }

    // epilogue: silu(g)*u, split fp16 hi/lo, planar store
    int wr = wid & 3, wc = wid >> 2;
#pragma unroll
    for (int mt = 0; mt < 2; mt++) {
        int rbse = row0 + wr * 32 + mt * 16 + (lane >> 2);
#pragma unroll
        for (int h2 = 0; h2 < 2; h2++) {
            int row = rbse + h2 * 8;
            if (row >= rend) continue;
            int colb = n0 + wc * 32 + (lane & 3) * 2;
            __half* hh = g_Hh + (size_t)row * HID + colb;
            __half* hl = g_Hl + (size_t)row * HID + colb;
#pragma unroll
            for (int nt = 0; nt < 4; nt++) {
                float g0 = acc1[mt][nt][h2 * 2 + 0], u0 = acc2[mt][nt][h2 * 2 + 0];
                float g1 = acc1[mt][nt][h2 * 2 + 1], u1 = acc2[mt][nt][h2 * 2 + 1];
                float hv0 = g0 * u0 / (1.f + expf(-g0));
                float hv1 = g1 * u1 / (1.f + expf(-g1));
                unsigned ph = hpack(hv0, hv1);
                float f0 = __half2float(__ushort_as_half((unsigned short)(ph & 0xffff)));
                float f1 = __half2float(__ushort_as_half((unsigned short)(ph >> 16)));
                unsigned pl = hpack(hv0 - f0, hv1 - f1);
                *(unsigned*)(hh + nt * 8) = ph;
                *(unsigned*)(hl + nt * 8) = pl;
            }
        }
    }
}

// ---------------- GEMM2 (M=128, N=128, 16 warps, warp tile 32x32) ----------------
__device__ __forceinline__ void comp2(uint32_t smb, int ast, int bst, int wid, int lane,
                                      float (&A)[2][4][4]) {
    int aoff = ast * A_STG;
    int boff = A_TOT + bst * B2_STG;
#pragma unroll
    for (int ks = 0; ks < 2; ks++) {
        uint32_t ah[2][4], al[2][4];
#pragma unroll
        for (int mt = 0; mt < 2; mt++) {
            int row = (wid & 3) * 32 + mt * 16 + (lane & 15);
            int hc = ks * 16 + ((lane & 16) >> 1);
            uint32_t ad = smb + (uint32_t)(aoff + row * ROWP + hc) * 2;
            ldm4(ah[mt][0], ah[mt][1], ah[mt][2], ah[mt][3], ad);
            ldm4(al[mt][0], al[mt][1], al[mt][2], al[mt][3], ad + 5120 * 2);
        }
        uint32_t bb[4][2];
#pragma unroll
        for (int p = 0; p < 2; p++) {
            int nr = (wid >> 2) * 32 + p * 16 + (lane & 7) + ((lane & 16) >> 1);
            int hc = ks * 16 + (lane & 8);
            uint32_t bd = smb + (uint32_t)(boff + nr * ROWP + hc) * 2;
            ldm4(bb[2*p][0], bb[2*p][1], bb[2*p+1][0], bb[2*p+1][1], bd);
        }
#pragma unroll
        for (int mt = 0; mt < 2; mt++)
#pragma unroll
            for (int nt = 0; nt < 4; nt++)
                mma16816(A[mt][nt], ah[mt], bb[nt]);
#pragma unroll
        for (int mt = 0; mt < 2; mt++)
#pragma unroll
            for (int nt = 0; nt < 4; nt++)
                mma16816(A[mt][nt], al[mt], bb[nt]);
    }
}

__device__ __forceinline__ void ldgB2(const float* __restrict__ w3, int k0, int tid, float4 (&r3)[2]) {
#pragma unroll
    for (int j = 0; j < 2; j++) {
        int idx = tid + (j << 9); int r = idx >> 3, cc = idx & 7;
        r3[j] = *(const float4*)(w3 + (size_t)r * HID + k0 + cc * 4);
    }
}
__device__ __forceinline__ void stsB2(uint16_t* sm16, int bst, int tid, const float4 (&r3)[2]) {
    int boff = A_TOT + bst * B2_STG;
#pragma unroll
    for (int j = 0; j < 2; j++) {
        int idx = tid + (j << 9); int r = idx >> 3, cc = idx & 7;
        *(ull*)(sm16 + boff + r * ROWP + cc * 4) = f4toh4(r3[j]);
    }
}

__global__ void __launch_bounds__(512, 1) k_ffn2(const float* __restrict__ W3,
                                                 float* __restrict__ out) {
    int e = blockIdx.z;
    int rbeg = g_off[e], rend = g_off[e + 1];
    int row0 = rbeg + blockIdx.y * 128;
    if (row0 >= rend) return;
    int n0 = blockIdx.x * 128;

    extern __shared__ __align__(16) uint16_t sm16[];
    __shared__ int s_row[128];
    int tid = threadIdx.x, wid = tid >> 5, lane = tid & 31;
    uint32_t smb = s2u(sm16);

    if (tid < 128) {
        int rr = row0 + tid;
        s_row[tid] = (rr < rend) ? rr : rbeg;
    }
    __syncthreads();

    const float* w3 = W3 + ((size_t)e * DIM + n0) * HID;

    float acc[2][4][4];
#pragma unroll
    for (int a = 0; a < 2; a++)
#pragma unroll
        for (int b = 0; b < 4; b++)
#pragma unroll
            for (int c = 0; c < 4; c++) acc[a][b][c] = 0.f;

    const int NC = HID / 32;  // 88
    cpA(smb, 0 * A_STG, tid, s_row, g_Hh, g_Hl, HID, 0);  CP_COMMIT();
    cpA(smb, 1 * A_STG, tid, s_row, g_Hh, g_Hl, HID, 32); CP_COMMIT();
    cpA(smb, 2 * A_STG, tid, s_row, g_Hh, g_Hl, HID, 64); CP_COMMIT();
    float4 r3[2];
    ldgB2(w3, 0, tid, r3);
    stsB2(sm16, 0, tid, r3);
    ldgB2(w3, 32, tid, r3);

    for (int c = 0; c < NC; c++) {
        CP_WAIT2();
        __syncthreads();
        if (c + 3 < NC) cpA(smb, ((c + 3) & 3) * A_STG, tid, s_row, g_Hh, g_Hl, HID, (c + 3) * 32);
        CP_COMMIT();
        if (c + 1 < NC) stsB2(sm16, (c + 1) & 1, tid, r3);
        if (c + 2 < NC) ldgB2(w3, (c + 2) * 32, tid, r3);
        comp2(smb, c & 3, c & 1, wid, lane, acc);
    }

    // epilogue: scale by gate weight, atomicAdd (2 contributors -> deterministic)
    int wr = wid & 3, wc = wid >> 2;
#pragma unroll
    for (int mt = 0; mt < 2; mt++) {
        int rbse = row0 + wr * 32 + mt * 16 + (lane >> 2);
#pragma unroll
        for (int h2 = 0; h2 < 2; h2++) {
            int slot = rbse + h2 * 8;
            if (slot >= rend) continue;
            int tk = g_tok[slot];
            float wv = g_wslot[slot];
            float* ob = out + (size_t)tk * DIM + n0 + wc * 32 + (lane & 3) * 2;
#pragma unroll
            for (int nt = 0; nt < 4; nt++) {
                atomicAdd(ob + nt * 8,     acc[mt][nt][h2 * 2 + 0] * wv);
                atomicAdd(ob + nt * 8 + 1, acc[mt][nt][h2 * 2 + 1] * wv);
            }
        }
    }
}

// ---------------- launch ----------------
extern "C" void kernel_launch(void* const* d_in, const int* in_sizes, int n_in,
                              void* d_out, int out_size) {
    const float* x  = (const float*)d_in[0];
    const float* Wg = (const float*)d_in[1];
    const float* W1 = (const float*)d_in[2];
    const float* W2 = (const float*)d_in[3];
    const float* W3 = (const float*)d_in[4];
    float* out = (float*)d_out;

    cudaFuncSetAttribute(k_ffn1, cudaFuncAttributeMaxDynamicSharedMemorySize, SMEM1);
    cudaFuncSetAttribute(k_ffn2, cudaFuncAttributeMaxDynamicSharedMemorySize, SMEM2);

    k_zero_cnt<<<1, 32>>>();
    k_zero_out<<<(T_TOK * DIM / 4) / 256, 256>>>((float4*)out);
    k_gate<<<T_TOK / 8, 256>>>(x, Wg);
    k_scan<<<1, 1>>>();
    k_assign<<<T_TOK / 256, 256>>>();
    k_ffn1<<<dim3(HID / 128, 32, NEXP), 512, SMEM1>>>(W1, W2);
    k_ffn2<<<dim3(DIM / 128, 32, NEXP), 512, SMEM2>>>(W3, out);
}

// round 12
// speedup vs baseline: 2.5112x; 1.5494x over previous
#include <cuda_runtime.h>
#include <cuda_fp16.h>
#include <math.h>
#include <stdint.h>

#define T_TOK 4096
#define DIM   1024
#define NEXP  8
#define HID   2816
#define NSLOT (T_TOK*2)

typedef unsigned long long ull;

// ---------------- device scratch (static, no allocs) ----------------
__device__ __align__(16) __half g_xh[(size_t)T_TOK*DIM];   // x as fp16
__device__ __align__(16) __half g_Hh[(size_t)NSLOT*HID];   // H as fp16
__device__ int   g_tok[NSLOT];
__device__ float g_wslot[NSLOT];
__device__ int   g_te[NSLOT];
__device__ float g_tw[NSLOT];
__device__ int   g_cnt[NEXP];
__device__ int   g_off[NEXP + 1];
__device__ int   g_cur[NEXP];

// ---------------- helpers ----------------
__device__ __forceinline__ uint32_t s2u(const void* p) {
    uint32_t a;
    asm("{ .reg .u64 t; cvta.to.shared.u64 t, %1; cvt.u32.u64 %0, t; }" : "=r"(a) : "l"(p));
    return a;
}
__device__ __forceinline__ unsigned hpack(float lo_elem, float hi_elem) {
    unsigned r;
    asm("cvt.rn.f16x2.f32 %0, %1, %2;" : "=r"(r) : "f"(hi_elem), "f"(lo_elem));
    return r;
}
__device__ __forceinline__ ull f4toh4(float4 v) {
    unsigned p0 = hpack(v.x, v.y);
    unsigned p1 = hpack(v.z, v.w);
    return (ull)p0 | ((ull)p1 << 32);
}
__device__ __forceinline__ void ldm4(uint32_t& r0, uint32_t& r1, uint32_t& r2, uint32_t& r3, uint32_t a) {
    asm volatile("ldmatrix.sync.aligned.m8n8.x4.shared.b16 {%0,%1,%2,%3}, [%4];"
        : "=r"(r0), "=r"(r1), "=r"(r2), "=r"(r3) : "r"(a));
}
__device__ __forceinline__ void mma16816(float* c, const uint32_t* a, const uint32_t* b) {
    asm volatile("mma.sync.aligned.m16n8k16.row.col.f32.f16.f16.f32 "
        "{%0,%1,%2,%3}, {%4,%5,%6,%7}, {%8,%9}, {%0,%1,%2,%3};"
        : "+f"(c[0]), "+f"(c[1]), "+f"(c[2]), "+f"(c[3])
        : "r"(a[0]), "r"(a[1]), "r"(a[2]), "r"(a[3]), "r"(b[0]), "r"(b[1]));
}
__device__ __forceinline__ void cpa16(uint32_t dst, const void* src) {
    asm volatile("cp.async.cg.shared.global [%0], [%1], 16;" :: "r"(dst), "l"(src) : "memory");
}
#define CP_COMMIT() asm volatile("cp.async.commit_group;" ::: "memory")
#define CP_WAIT2()  asm volatile("cp.async.wait_group 2;" ::: "memory")

// smem geometry (halves): rows padded to 40 (k32 + 8)
#define ROWP   40
#define A_STG  5120                  // A (128 rows, single fp16 plane) per stage
#define A_TOT  (4*A_STG)
#define B1_STG 10240                 // B1(5120)+B2(5120), 128 N-rows each
#define B2_STG 5120                  // B(5120), 128 N-rows
#define SMEM1  ((A_TOT + 2*B1_STG)*2)   // 81920
#define SMEM2  ((A_TOT + 2*B2_STG)*2)   // 61440

// ---------------- small kernels ----------------
__global__ void k_zero_cnt() { if (threadIdx.x < NEXP) g_cnt[threadIdx.x] = 0; }

__global__ void k_zero_out(float4* o) {
    o[blockIdx.x * 256 + threadIdx.x] = make_float4(0.f, 0.f, 0.f, 0.f);
}

// gating + convert x to fp16
__global__ void k_gate(const float* __restrict__ x, const float* __restrict__ Wg) {
    int t = (blockIdx.x * blockDim.x + threadIdx.x) >> 5;
    int lane = threadIdx.x & 31;
    if (t >= T_TOK) return;
    const float4* xr = reinterpret_cast<const float4*>(x + (size_t)t * DIM);
    float s[NEXP];
#pragma unroll
    for (int e = 0; e < NEXP; e++) s[e] = 0.f;
    for (int i = lane; i < DIM / 4; i += 32) {
        float4 xv = xr[i];
#pragma unroll
        for (int e = 0; e < NEXP; e++) {
            float4 wv = reinterpret_cast<const float4*>(Wg + (size_t)e * DIM)[i];
            s[e] += xv.x * wv.x + xv.y * wv.y + xv.z * wv.z + xv.w * wv.w;
        }
        unsigned h01 = hpack(xv.x, xv.y);
        unsigned h23 = hpack(xv.z, xv.w);
        *(uint2*)(g_xh + (size_t)t * DIM + i * 4) = make_uint2(h01, h23);
    }
#pragma unroll
    for (int e = 0; e < NEXP; e++) {
#pragma unroll
        for (int o = 16; o > 0; o >>= 1) s[e] += __shfl_xor_sync(0xffffffffu, s[e], o);
    }
    if (lane == 0) {
        int b0 = 0; float v0 = s[0];
#pragma unroll
        for (int e = 1; e < NEXP; e++) if (s[e] > v0) { v0 = s[e]; b0 = e; }
        int b1 = -1; float v1 = -3.4e38f;
#pragma unroll
        for (int e = 0; e < NEXP; e++) if (e != b0 && s[e] > v1) { v1 = s[e]; b1 = e; }
        g_te[t * 2 + 0] = b0;  g_te[t * 2 + 1] = b1;
        g_tw[t * 2 + 0] = v0;  g_tw[t * 2 + 1] = v1;
        atomicAdd(&g_cnt[b0], 1);
        atomicAdd(&g_cnt[b1], 1);
    }
}

__global__ void k_scan() {
    int o = 0;
    for (int e = 0; e < NEXP; e++) { g_off[e] = o; g_cur[e] = o; o += g_cnt[e]; }
    g_off[NEXP] = o;
}

__global__ void k_assign() {
    int t = blockIdx.x * blockDim.x + threadIdx.x;
    if (t >= T_TOK) return;
#pragma unroll
    for (int k = 0; k < 2; k++) {
        int e = g_te[t * 2 + k];
        int pos = atomicAdd(&g_cur[e], 1);
        g_tok[pos] = t;
        g_wslot[pos] = g_tw[t * 2 + k];
    }
}

// ---------------- A staging: 1 cp.async per thread (512 threads, 128 rows x 32 halves) ----------------
__device__ __forceinline__ void cpA(uint32_t smb, int soff, int tid, const int* s_idx,
                                    const __half* __restrict__ ah, int rowstride, int k0) {
    int r = tid >> 2, g = tid & 3;
    size_t so = (size_t)s_idx[r] * rowstride + k0 + g * 8;
    uint32_t d = smb + (uint32_t)(soff + r * ROWP + g * 8) * 2;
    cpa16(d, ah + so);
}

// ---------------- GEMM1 (M=128, N=128, 16 warps, warp tile 32x32) ----------------
__device__ __forceinline__ void comp1(uint32_t smb, int ast, int bst, int wid, int lane,
                                      float (&A1)[2][4][4], float (&A2)[2][4][4]) {
    int aoff = ast * A_STG;
    int boff = A_TOT + bst * B1_STG;
#pragma unroll
    for (int ks = 0; ks < 2; ks++) {
        uint32_t ah[2][4];
#pragma unroll
        for (int mt = 0; mt < 2; mt++) {
            int row = (wid & 3) * 32 + mt * 16 + (lane & 15);
            int hc = ks * 16 + ((lane & 16) >> 1);
            uint32_t ad = smb + (uint32_t)(aoff + row * ROWP + hc) * 2;
            ldm4(ah[mt][0], ah[mt][1], ah[mt][2], ah[mt][3], ad);
        }
        uint32_t b1[4][2], b2[4][2];
#pragma unroll
        for (int p = 0; p < 2; p++) {
            int nr = (wid >> 2) * 32 + p * 16 + (lane & 7) + ((lane & 16) >> 1);
            int hc = ks * 16 + (lane & 8);
            uint32_t bd = smb + (uint32_t)(boff + nr * ROWP + hc) * 2;
            ldm4(b1[2*p][0], b1[2*p][1], b1[2*p+1][0], b1[2*p+1][1], bd);
            ldm4(b2[2*p][0], b2[2*p][1], b2[2*p+1][0], b2[2*p+1][1], bd + 5120 * 2);
        }
#pragma unroll
        for (int mt = 0; mt < 2; mt++)
#pragma unroll
            for (int nt = 0; nt < 4; nt++) {
                mma16816(A1[mt][nt], ah[mt], b1[nt]);
                mma16816(A2[mt][nt], ah[mt], b2[nt]);
            }
    }
}

__device__ __forceinline__ void ldgB1(const float* __restrict__ w1, const float* __restrict__ w2,
                                      int k0, int tid, float4 (&r1)[2], float4 (&r2)[2]) {
#pragma unroll
    for (int j = 0; j < 2; j++) {
        int idx = tid + (j << 9); int r = idx >> 3, cc = idx & 7;
        r1[j] = *(const float4*)(w1 + (size_t)r * DIM + k0 + cc * 4);
        r2[j] = *(const float4*)(w2 + (size_t)r * DIM + k0 + cc * 4);
    }
}
__device__ __forceinline__ void stsB1(uint16_t* sm16, int bst, int tid,
                                      const float4 (&r1)[2], const float4 (&r2)[2]) {
    int boff = A_TOT + bst * B1_STG;
#pragma unroll
    for (int j = 0; j < 2; j++) {
        int idx = tid + (j << 9); int r = idx >> 3, cc = idx & 7;
        *(ull*)(sm16 + boff + r * ROWP + cc * 4) = f4toh4(r1[j]);
        *(ull*)(sm16 + boff + 5120 + r * ROWP + cc * 4) = f4toh4(r2[j]);
    }
}

__global__ void __launch_bounds__(512, 1) k_ffn1(const float* __restrict__ W1,
                                                 const float* __restrict__ W2) {
    int e = blockIdx.z;
    int rbeg = g_off[e], rend = g_off[e + 1];
    int row0 = rbeg + blockIdx.y * 128;
    if (row0 >= rend) return;
    int n0 = blockIdx.x * 128;

    extern __shared__ __align__(16) uint16_t sm16[];
    __shared__ int s_tok[128];
    int tid = threadIdx.x, wid = tid >> 5, lane = tid & 31;
    uint32_t smb = s2u(sm16);

    if (tid < 128) {
        int rr = row0 + tid;
        s_tok[tid] = g_tok[rr < rend ? rr : rbeg];
    }
    __syncthreads();

    const float* w1 = W1 + ((size_t)e * HID + n0) * DIM;
    const float* w2 = W2 + ((size_t)e * HID + n0) * DIM;

    float acc1[2][4][4], acc2[2][4][4];
#pragma unroll
    for (int a = 0; a < 2; a++)
#pragma unroll
        for (int b = 0; b < 4; b++)
#pragma unroll
            for (int c = 0; c < 4; c++) { acc1[a][b][c] = 0.f; acc2[a][b][c] = 0.f; }

    const int NC = DIM / 32;  // 32
    cpA(smb, 0 * A_STG, tid, s_tok, g_xh, DIM, 0);  CP_COMMIT();
    cpA(smb, 1 * A_STG, tid, s_tok, g_xh, DIM, 32); CP_COMMIT();
    cpA(smb, 2 * A_STG, tid, s_tok, g_xh, DIM, 64); CP_COMMIT();
    float4 r1[2], r2[2];
    ldgB1(w1, w2, 0, tid, r1, r2);
    stsB1(sm16, 0, tid, r1, r2);
    ldgB1(w1, w2, 32, tid, r1, r2);

    for (int c = 0; c < NC; c++) {
        CP_WAIT2();
        __syncthreads();
        if (c + 3 < NC) cpA(smb, ((c + 3) & 3) * A_STG, tid, s_tok, g_xh, DIM, (c + 3) * 32);
        CP_COMMIT();
        if (c + 1 < NC) stsB1(sm16, (c + 1) & 1, tid, r1, r2);
        if (c + 2 < NC) ldgB1(w1, w2, (c + 2) * 32, tid, r1, r2);
        comp1(smb, c & 3, c & 1, wid, lane, acc1, acc2);
    }

    // epilogue: silu(g)*u -> fp16 store
    int wr = wid & 3, wc = wid >> 2;
#pragma unroll
    for (int mt = 0; mt < 2; mt++) {
        int rbse = row0 + wr * 32 + mt * 16 + (lane >> 2);
#pragma unroll
        for (int h2 = 0; h2 < 2; h2++) {
            int row = rbse + h2 * 8;
            if (row >= rend) continue;
            int colb = n0 + wc * 32 + (lane & 3) * 2;
            __half* hh = g_Hh + (size_t)row * HID + colb;
#pragma unroll
            for (int nt = 0; nt < 4; nt++) {
                float g0 = acc1[mt][nt][h2 * 2 + 0], u0 = acc2[mt][nt][h2 * 2 + 0];
                float g1 = acc1[mt][nt][h2 * 2 + 1], u1 = acc2[mt][nt][h2 * 2 + 1];
                float hv0 = g0 * u0 / (1.f + expf(-g0));
                float hv1 = g1 * u1 / (1.f + expf(-g1));
                *(unsigned*)(hh + nt * 8) = hpack(hv0, hv1);
            }
        }
    }
}

// ---------------- GEMM2 (M=128, N=128, 16 warps, warp tile 32x32) ----------------
__device__ __forceinline__ void comp2(uint32_t smb, int ast, int bst, int wid, int lane,
                                      float (&A)[2][4][4]) {
    int aoff = ast * A_STG;
    int boff = A_TOT + bst * B2_STG;
#pragma unroll
    for (int ks = 0; ks < 2; ks++) {
        uint32_t ah[2][4];
#pragma unroll
        for (int mt = 0; mt < 2; mt++) {
            int row = (wid & 3) * 32 + mt * 16 + (lane & 15);
            int hc = ks * 16 + ((lane & 16) >> 1);
            uint32_t ad = smb + (uint32_t)(aoff + row * ROWP + hc) * 2;
            ldm4(ah[mt][0], ah[mt][1], ah[mt][2], ah[mt][3], ad);
        }
        uint32_t bb[4][2];
#pragma unroll
        for (int p = 0; p < 2; p++) {
            int nr = (wid >> 2) * 32 + p * 16 + (lane & 7) + ((lane & 16) >> 1);
            int hc = ks * 16 + (lane & 8);
            uint32_t bd = smb + (uint32_t)(boff + nr * ROWP + hc) * 2;
            ldm4(bb[2*p][0], bb[2*p][1], bb[2*p+1][0], bb[2*p+1][1], bd);
        }
#pragma unroll
        for (int mt = 0; mt < 2; mt++)
#pragma unroll
            for (int nt = 0; nt < 4; nt++)
                mma16816(A[mt][nt], ah[mt], bb[nt]);
    }
}

__device__ __forceinline__ void ldgB2(const float* __restrict__ w3, int k0, int tid, float4 (&r3)[2]) {
#pragma unroll
    for (int j = 0; j < 2; j++) {
        int idx = tid + (j << 9); int r = idx >> 3, cc = idx & 7;
        r3[j] = *(const float4*)(w3 + (size_t)r * HID + k0 + cc * 4);
    }
}
__device__ __forceinline__ void stsB2(uint16_t* sm16, int bst, int tid, const float4 (&r3)[2]) {
    int boff = A_TOT + bst * B2_STG;
#pragma unroll
    for (int j = 0; j < 2; j++) {
        int idx = tid + (j << 9); int r = idx >> 3, cc = idx & 7;
        *(ull*)(sm16 + boff + r * ROWP + cc * 4) = f4toh4(r3[j]);
    }
}

__global__ void __launch_bounds__(512, 1) k_ffn2(const float* __restrict__ W3,
                                                 float* __restrict__ out) {
    int e = blockIdx.z;
    int rbeg = g_off[e], rend = g_off[e + 1];
    int row0 = rbeg + blockIdx.y * 128;
    if (row0 >= rend) return;
    int n0 = blockIdx.x * 128;

    extern __shared__ __align__(16) uint16_t sm16[];
    __shared__ int s_row[128];
    int tid = threadIdx.x, wid = tid >> 5, lane = tid & 31;
    uint32_t smb = s2u(sm16);

    if (tid < 128) {
        int rr = row0 + tid;
        s_row[tid] = (rr < rend) ? rr : rbeg;
    }
    __syncthreads();

    const float* w3 = W3 + ((size_t)e * DIM + n0) * HID;

    float acc[2][4][4];
#pragma unroll
    for (int a = 0; a < 2; a++)
#pragma unroll
        for (int b = 0; b < 4; b++)
#pragma unroll
            for (int c = 0; c < 4; c++) acc[a][b][c] = 0.f;

    const int NC = HID / 32;  // 88
    cpA(smb, 0 * A_STG, tid, s_row, g_Hh, HID, 0);  CP_COMMIT();
    cpA(smb, 1 * A_STG, tid, s_row, g_Hh, HID, 32); CP_COMMIT();
    cpA(smb, 2 * A_STG, tid, s_row, g_Hh, HID, 64); CP_COMMIT();
    float4 r3[2];
    ldgB2(w3, 0, tid, r3);
    stsB2(sm16, 0, tid, r3);
    ldgB2(w3, 32, tid, r3);

    for (int c = 0; c < NC; c++) {
        CP_WAIT2();
        __syncthreads();
        if (c + 3 < NC) cpA(smb, ((c + 3) & 3) * A_STG, tid, s_row, g_Hh, HID, (c + 3) * 32);
        CP_COMMIT();
        if (c + 1 < NC) stsB2(sm16, (c + 1) & 1, tid, r3);
        if (c + 2 < NC) ldgB2(w3, (c + 2) * 32, tid, r3);
        comp2(smb, c & 3, c & 1, wid, lane, acc);
    }

    // epilogue: scale by gate weight, atomicAdd (2 contributors -> deterministic)
    int wr = wid & 3, wc = wid >> 2;
#pragma unroll
    for (int mt = 0; mt < 2; mt++) {
        int rbse = row0 + wr * 32 + mt * 16 + (lane >> 2);
#pragma unroll
        for (int h2 = 0; h2 < 2; h2++) {
            int slot = rbse + h2 * 8;
            if (slot >= rend) continue;
            int tk = g_tok[slot];
            float wv = g_wslot[slot];
            float* ob = out + (size_t)tk * DIM + n0 + wc * 32 + (lane & 3) * 2;
#pragma unroll
            for (int nt = 0; nt < 4; nt++) {
                atomicAdd(ob + nt * 8,     acc[mt][nt][h2 * 2 + 0] * wv);
                atomicAdd(ob + nt * 8 + 1, acc[mt][nt][h2 * 2 + 1] * wv);
            }
        }
    }
}

// ---------------- launch ----------------
extern "C" void kernel_launch(void* const* d_in, const int* in_sizes, int n_in,
                              void* d_out, int out_size) {
    const float* x  = (const float*)d_in[0];
    const float* Wg = (const float*)d_in[1];
    const float* W1 = (const float*)d_in[2];
    const float* W2 = (const float*)d_in[3];
    const float* W3 = (const float*)d_in[4];
    float* out = (float*)d_out;

    cudaFuncSetAttribute(k_ffn1, cudaFuncAttributeMaxDynamicSharedMemorySize, SMEM1);
    cudaFuncSetAttribute(k_ffn2, cudaFuncAttributeMaxDynamicSharedMemorySize, SMEM2);

    k_zero_cnt<<<1, 32>>>();
    k_zero_out<<<(T_TOK * DIM / 4) / 256, 256>>>((float4*)out);
    k_gate<<<T_TOK / 8, 256>>>(x, Wg);
    k_scan<<<1, 1>>>();
    k_assign<<<T_TOK / 256, 256>>>();
    k_ffn1<<<dim3(HID / 128, 32, NEXP), 512, SMEM1>>>(W1, W2);
    k_ffn2<<<dim3(DIM / 128, 32, NEXP), 512, SMEM2>>>(W3, out);
}

// round 15
// speedup vs baseline: 2.8528x; 1.1360x over previous
#include <cuda_runtime.h>
#include <cuda_fp16.h>
#include <math.h>
#include <stdint.h>

#define T_TOK 4096
#define DIM   1024
#define NEXP  8
#define HID   2816
#define NSLOT (T_TOK*2)

typedef unsigned long long ull;

// ---------------- device scratch (static, no allocs) ----------------
__device__ __align__(16) __half g_W1h[(size_t)NEXP*HID*DIM];  // 46.2MB
__device__ __align__(16) __half g_W2h[(size_t)NEXP*HID*DIM];
__device__ __align__(16) __half g_W3h[(size_t)NEXP*DIM*HID];
__device__ __align__(16) __half g_xh[(size_t)T_TOK*DIM];
__device__ __align__(16) __half g_Hh[(size_t)NSLOT*HID];
__device__ int   g_tok[NSLOT];
__device__ float g_wslot[NSLOT];
__device__ int   g_te[NSLOT];
__device__ float g_tw[NSLOT];
__device__ int   g_cnt[NEXP];
__device__ int   g_off[NEXP + 1];
__device__ int   g_cur[NEXP];

// ---------------- helpers ----------------
__device__ __forceinline__ uint32_t s2u(const void* p) {
    uint32_t a;
    asm("{ .reg .u64 t; cvta.to.shared.u64 t, %1; cvt.u32.u64 %0, t; }" : "=r"(a) : "l"(p));
    return a;
}
__device__ __forceinline__ unsigned hpack(float lo_elem, float hi_elem) {
    unsigned r;
    asm("cvt.rn.f16x2.f32 %0, %1, %2;" : "=r"(r) : "f"(hi_elem), "f"(lo_elem));
    return r;
}
__device__ __forceinline__ ull f4toh4(float4 v) {
    unsigned p0 = hpack(v.x, v.y);
    unsigned p1 = hpack(v.z, v.w);
    return (ull)p0 | ((ull)p1 << 32);
}
__device__ __forceinline__ void ldm4(uint32_t& r0, uint32_t& r1, uint32_t& r2, uint32_t& r3, uint32_t a) {
    asm volatile("ldmatrix.sync.aligned.m8n8.x4.shared.b16 {%0,%1,%2,%3}, [%4];"
        : "=r"(r0), "=r"(r1), "=r"(r2), "=r"(r3) : "r"(a));
}
__device__ __forceinline__ void mma16816(float* c, const uint32_t* a, const uint32_t* b) {
    asm volatile("mma.sync.aligned.m16n8k16.row.col.f32.f16.f16.f32 "
        "{%0,%1,%2,%3}, {%4,%5,%6,%7}, {%8,%9}, {%0,%1,%2,%3};"
        : "+f"(c[0]), "+f"(c[1]), "+f"(c[2]), "+f"(c[3])
        : "r"(a[0]), "r"(a[1]), "r"(a[2]), "r"(a[3]), "r"(b[0]), "r"(b[1]));
}
__device__ __forceinline__ void cpa16(uint32_t dst, const void* src) {
    asm volatile("cp.async.cg.shared.global [%0], [%1], 16;" :: "r"(dst), "l"(src) : "memory");
}
#define CP_COMMIT() asm volatile("cp.async.commit_group;" ::: "memory")
#define CP_WAIT2()  asm volatile("cp.async.wait_group 2;" ::: "memory")

// smem geometry (halves): rows padded to 40 (k32 + 8)
#define ROWP   40
#define S1_STG 15360                 // A(5120) + B1(5120) + B2(5120)
#define S2_STG 10240                 // A(5120) + B(5120)
#define SMEM1  (4*S1_STG*2)          // 122880
#define SMEM2  (4*S2_STG*2)          // 81920

// ---------------- small kernels ----------------
__global__ void k_cvtw(const float4* __restrict__ W1, const float4* __restrict__ W2,
                       const float4* __restrict__ W3) {
    const size_t n1 = (size_t)NEXP * HID * DIM / 4;
    size_t i0 = (size_t)blockIdx.x * blockDim.x + threadIdx.x;
    if (i0 < NEXP) g_cnt[i0] = 0;
    size_t stride = (size_t)gridDim.x * blockDim.x;
    for (size_t i = i0; i < n1; i += stride) {
        *(ull*)(g_W1h + i * 4) = f4toh4(W1[i]);
        *(ull*)(g_W2h + i * 4) = f4toh4(W2[i]);
        *(ull*)(g_W3h + i * 4) = f4toh4(W3[i]);
    }
}

__global__ void k_zero_out(float4* o) {
    o[blockIdx.x * 256 + threadIdx.x] = make_float4(0.f, 0.f, 0.f, 0.f);
}

// gating + convert x to fp16
__global__ void k_gate(const float* __restrict__ x, const float* __restrict__ Wg) {
    int t = (blockIdx.x * blockDim.x + threadIdx.x) >> 5;
    int lane = threadIdx.x & 31;
    if (t >= T_TOK) return;
    const float4* xr = reinterpret_cast<const float4*>(x + (size_t)t * DIM);
    float s[NEXP];
#pragma unroll
    for (int e = 0; e < NEXP; e++) s[e] = 0.f;
    for (int i = lane; i < DIM / 4; i += 32) {
        float4 xv = xr[i];
#pragma unroll
        for (int e = 0; e < NEXP; e++) {
            float4 wv = reinterpret_cast<const float4*>(Wg + (size_t)e * DIM)[i];
            s[e] += xv.x * wv.x + xv.y * wv.y + xv.z * wv.z + xv.w * wv.w;
        }
        unsigned h01 = hpack(xv.x, xv.y);
        unsigned h23 = hpack(xv.z, xv.w);
        *(uint2*)(g_xh + (size_t)t * DIM + i * 4) = make_uint2(h01, h23);
    }
#pragma unroll
    for (int e = 0; e < NEXP; e++) {
#pragma unroll
        for (int o = 16; o > 0; o >>= 1) s[e] += __shfl_xor_sync(0xffffffffu, s[e], o);
    }
    if (lane == 0) {
        int b0 = 0; float v0 = s[0];
#pragma unroll
        for (int e = 1; e < NEXP; e++) if (s[e] > v0) { v0 = s[e]; b0 = e; }
        int b1 = -1; float v1 = -3.4e38f;
#pragma unroll
        for (int e = 0; e < NEXP; e++) if (e != b0 && s[e] > v1) { v1 = s[e]; b1 = e; }
        g_te[t * 2 + 0] = b0;  g_te[t * 2 + 1] = b1;
        g_tw[t * 2 + 0] = v0;  g_tw[t * 2 + 1] = v1;
        atomicAdd(&g_cnt[b0], 1);
        atomicAdd(&g_cnt[b1], 1);
    }
}

__global__ void k_scan() {
    int o = 0;
    for (int e = 0; e < NEXP; e++) { g_off[e] = o; g_cur[e] = o; o += g_cnt[e]; }
    g_off[NEXP] = o;
}

__global__ void k_assign() {
    int t = blockIdx.x * blockDim.x + threadIdx.x;
    if (t >= T_TOK) return;
#pragma unroll
    for (int k = 0; k < 2; k++) {
        int e = g_te[t * 2 + k];
        int pos = atomicAdd(&g_cur[e], 1);
        g_tok[pos] = t;
        g_wslot[pos] = g_tw[t * 2 + k];
    }
}

// ---------------- stage issue: all cp.async, 512 threads ----------------
// GEMM1: A(x rows) + B1(W1) + B2(W2); 3 x 16B per thread
__device__ __forceinline__ void issue1(uint32_t smb, int soff, int tid, const int* s_tok,
        const __half* __restrict__ b1, const __half* __restrict__ b2, int k0) {
    int r = tid >> 2, g = tid & 3;
    uint32_t d = smb + (uint32_t)(soff + r * ROWP + g * 8) * 2;
    cpa16(d, g_xh + (size_t)s_tok[r] * DIM + k0 + g * 8);
    size_t wo = (size_t)r * DIM + k0 + g * 8;
    cpa16(d + 5120 * 2, b1 + wo);
    cpa16(d + 10240 * 2, b2 + wo);
}
// GEMM2: A(H rows) + B(W3); 2 x 16B per thread
__device__ __forceinline__ void issue2(uint32_t smb, int soff, int tid, const int* s_row,
        const __half* __restrict__ b3, int k0) {
    int r = tid >> 2, g = tid & 3;
    uint32_t d = smb + (uint32_t)(soff + r * ROWP + g * 8) * 2;
    cpa16(d, g_Hh + (size_t)s_row[r] * HID + k0 + g * 8);
    cpa16(d + 5120 * 2, b3 + (size_t)r * HID + k0 + g * 8);
}

// ---------------- GEMM1 (M=128, N=128, 16 warps, warp tile 32x32) ----------------
__device__ __forceinline__ void comp1(uint32_t smb, int st, int wid, int lane,
                                      float (&A1)[2][4][4], float (&A2)[2][4][4]) {
    int aoff = st * S1_STG;
    int boff = aoff + 5120;
#pragma unroll
    for (int ks = 0; ks < 2; ks++) {
        uint32_t ah[2][4];
#pragma unroll
        for (int mt = 0; mt < 2; mt++) {
            int row = (wid & 3) * 32 + mt * 16 + (lane & 15);
            int hc = ks * 16 + ((lane & 16) >> 1);
            uint32_t ad = smb + (uint32_t)(aoff + row * ROWP + hc) * 2;
            ldm4(ah[mt][0], ah[mt][1], ah[mt][2], ah[mt][3], ad);
        }
        uint32_t b1[4][2], b2[4][2];
#pragma unroll
        for (int p = 0; p < 2; p++) {
            int nr = (wid >> 2) * 32 + p * 16 + (lane & 7) + ((lane & 16) >> 1);
            int hc = ks * 16 + (lane & 8);
            uint32_t bd = smb + (uint32_t)(boff + nr * ROWP + hc) * 2;
            ldm4(b1[2*p][0], b1[2*p][1], b1[2*p+1][0], b1[2*p+1][1], bd);
            ldm4(b2[2*p][0], b2[2*p][1], b2[2*p+1][0], b2[2*p+1][1], bd + 5120 * 2);
        }
#pragma unroll
        for (int mt = 0; mt < 2; mt++)
#pragma unroll
            for (int nt = 0; nt < 4; nt++) {
                mma16816(A1[mt][nt], ah[mt], b1[nt]);
                mma16816(A2[mt][nt], ah[mt], b2[nt]);
            }
    }
}

__global__ void __launch_bounds__(512, 1) k_ffn1() {
    int e = blockIdx.z;
    int rbeg = g_off[e], rend = g_off[e + 1];
    int row0 = rbeg + blockIdx.x * 128;   // x = row tile (B-sharing across consecutive CTAs)
    if (row0 >= rend) return;
    int n0 = blockIdx.y * 128;            // y = col tile

    extern __shared__ __align__(16) uint16_t sm16[];
    __shared__ int s_tok[128];
    int tid = threadIdx.x, wid = tid >> 5, lane = tid & 31;
    uint32_t smb = s2u(sm16);

    if (tid < 128) {
        int rr = row0 + tid;
        s_tok[tid] = g_tok[rr < rend ? rr : rbeg];
    }
    __syncthreads();

    const __half* b1 = g_W1h + ((size_t)e * HID + n0) * DIM;
    const __half* b2 = g_W2h + ((size_t)e * HID + n0) * DIM;

    float acc1[2][4][4], acc2[2][4][4];
#pragma unroll
    for (int a = 0; a < 2; a++)
#pragma unroll
        for (int b = 0; b < 4; b++)
#pragma unroll
            for (int c = 0; c < 4; c++) { acc1[a][b][c] = 0.f; acc2[a][b][c] = 0.f; }

    const int NC = DIM / 32;  // 32
    issue1(smb, 0 * S1_STG, tid, s_tok, b1, b2, 0);  CP_COMMIT();
    issue1(smb, 1 * S1_STG, tid, s_tok, b1, b2, 32); CP_COMMIT();
    issue1(smb, 2 * S1_STG, tid, s_tok, b1, b2, 64); CP_COMMIT();

    for (int c = 0; c < NC; c++) {
        CP_WAIT2();
        __syncthreads();
        if (c + 3 < NC) issue1(smb, ((c + 3) & 3) * S1_STG, tid, s_tok, b1, b2, (c + 3) * 32);
        CP_COMMIT();
        comp1(smb, c & 3, wid, lane, acc1, acc2);
    }

    // epilogue: silu(g)*u -> fp16 store
    int wr = wid & 3, wc = wid >> 2;
#pragma unroll
    for (int mt = 0; mt < 2; mt++) {
        int rbse = row0 + wr * 32 + mt * 16 + (lane >> 2);
#pragma unroll
        for (int h2 = 0; h2 < 2; h2++) {
            int row = rbse + h2 * 8;
            if (row >= rend) continue;
            int colb = n0 + wc * 32 + (lane & 3) * 2;
            __half* hh = g_Hh + (size_t)row * HID + colb;
#pragma unroll
            for (int nt = 0; nt < 4; nt++) {
                float g0 = acc1[mt][nt][h2 * 2 + 0], u0 = acc2[mt][nt][h2 * 2 + 0];
                float g1 = acc1[mt][nt][h2 * 2 + 1], u1 = acc2[mt][nt][h2 * 2 + 1];
                float hv0 = g0 * u0 / (1.f + expf(-g0));
                float hv1 = g1 * u1 / (1.f + expf(-g1));
                *(unsigned*)(hh + nt * 8) = hpack(hv0, hv1);
            }
        }
    }
}

// ---------------- GEMM2 (M=128, N=128, 16 warps, warp tile 32x32) ----------------
__device__ __forceinline__ void comp2(uint32_t smb, int st, int wid, int lane,
                                      float (&A)[2][4][4]) {
    int aoff = st * S2_STG;
    int boff = aoff + 5120;
#pragma unroll
    for (int ks = 0; ks < 2; ks++) {
        uint32_t ah[2][4];
#pragma unroll
        for (int mt = 0; mt < 2; mt++) {
            int row = (wid & 3) * 32 + mt * 16 + (lane & 15);
            int hc = ks * 16 + ((lane & 16) >> 1);
            uint32_t ad = smb + (uint32_t)(aoff + row * ROWP + hc) * 2;
            ldm4(ah[mt][0], ah[mt][1], ah[mt][2], ah[mt][3], ad);
        }
        uint32_t bb[4][2];
#pragma unroll
        for (int p = 0; p < 2; p++) {
            int nr = (wid >> 2) * 32 + p * 16 + (lane & 7) + ((lane & 16) >> 1);
            int hc = ks * 16 + (lane & 8);
            uint32_t bd = smb + (uint32_t)(boff + nr * ROWP + hc) * 2;
            ldm4(bb[2*p][0], bb[2*p][1], bb[2*p+1][0], bb[2*p+1][1], bd);
        }
#pragma unroll
        for (int mt = 0; mt < 2; mt++)
#pragma unroll
            for (int nt = 0; nt < 4; nt++)
                mma16816(A[mt][nt], ah[mt], bb[nt]);
    }
}

__global__ void __launch_bounds__(512, 1) k_ffn2(float* __restrict__ out) {
    int e = blockIdx.z;
    int rbeg = g_off[e], rend = g_off[e + 1];
    int row0 = rbeg + blockIdx.x * 128;   // x = row tile
    if (row0 >= rend) return;
    int n0 = blockIdx.y * 128;            // y = col tile

    extern __shared__ __align__(16) uint16_t sm16[];
    __shared__ int s_row[128];
    int tid = threadIdx.x, wid = tid >> 5, lane = tid & 31;
    uint32_t smb = s2u(sm16);

    if (tid < 128) {
        int rr = row0 + tid;
        s_row[tid] = (rr < rend) ? rr : rbeg;
    }
    __syncthreads();

    const __half* b3 = g_W3h + ((size_t)e * DIM + n0) * HID;

    float acc[2][4][4];
#pragma unroll
    for (int a = 0; a < 2; a++)
#pragma unroll
        for (int b = 0; b < 4; b++)
#pragma unroll
            for (int c = 0; c < 4; c++) acc[a][b][c] = 0.f;

    const int NC = HID / 32;  // 88
    issue2(smb, 0 * S2_STG, tid, s_row, b3, 0);  CP_COMMIT();
    issue2(smb, 1 * S2_STG, tid, s_row, b3, 32); CP_COMMIT();
    issue2(smb, 2 * S2_STG, tid, s_row, b3, 64); CP_COMMIT();

    for (int c = 0; c < NC; c++) {
        CP_WAIT2();
        __syncthreads();
        if (c + 3 < NC) issue2(smb, ((c + 3) & 3) * S2_STG, tid, s_row, b3, (c + 3) * 32);
        CP_COMMIT();
        comp2(smb, c & 3, wid, lane, acc);
    }

    // epilogue: scale by gate weight, atomicAdd (2 contributors -> deterministic)
    int wr = wid & 3, wc = wid >> 2;
#pragma unroll
    for (int mt = 0; mt < 2; mt++) {
        int rbse = row0 + wr * 32 + mt * 16 + (lane >> 2);
#pragma unroll
        for (int h2 = 0; h2 < 2; h2++) {
            int slot = rbse + h2 * 8;
            if (slot >= rend) continue;
            int tk = g_tok[slot];
            float wv = g_wslot[slot];
            float* ob = out + (size_t)tk * DIM + n0 + wc * 32 + (lane & 3) * 2;
#pragma unroll
            for (int nt = 0; nt < 4; nt++) {
                atomicAdd(ob + nt * 8,     acc[mt][nt][h2 * 2 + 0] * wv);
                atomicAdd(ob + nt * 8 + 1, acc[mt][nt][h2 * 2 + 1] * wv);
            }
        }
    }
}

// ---------------- launch ----------------
extern "C" void kernel_launch(void* const* d_in, const int* in_sizes, int n_in,
                              void* d_out, int out_size) {
    const float* x  = (const float*)d_in[0];
    const float* Wg = (const float*)d_in[1];
    const float* W1 = (const float*)d_in[2];
    const float* W2 = (const float*)d_in[3];
    const float* W3 = (const float*)d_in[4];
    float* out = (float*)d_out;

    cudaFuncSetAttribute(k_ffn1, cudaFuncAttributeMaxDynamicSharedMemorySize, SMEM1);
    cudaFuncSetAttribute(k_ffn2, cudaFuncAttributeMaxDynamicSharedMemorySize, SMEM2);

    k_cvtw<<<2048, 256>>>((const float4*)W1, (const float4*)W2, (const float4*)W3);
    k_zero_out<<<(T_TOK * DIM / 4) / 256, 256>>>((float4*)out);
    k_gate<<<T_TOK / 8, 256>>>(x, Wg);
    k_scan<<<1, 1>>>();
    k_assign<<<T_TOK / 256, 256>>>();
    k_ffn1<<<dim3(32, HID / 128, NEXP), 512, SMEM1>>>();
    k_ffn2<<<dim3(32, DIM / 128, NEXP), 512, SMEM2>>>(out);
}